// round 6
// baseline (speedup 1.0000x reference)
#include <cuda_runtime.h>
#include <cuda_bf16.h>
#include <cstdint>

#define PKE 134217728   // 4096*8*64*64

// Scratch (__device__ globals; allocation-free rule)
__device__ __nv_bfloat16 g_xh[PKE], g_xl[PKE];     // x split
__device__ __nv_bfloat16 g_qh[PKE], g_ql[PKE];     // q split, [B,H,N,64], pre-scaled
__device__ __nv_bfloat16 g_aoh[PKE], g_aol[PKE];   // attn out split, [B*N,512]
__device__ __nv_bfloat16 g_wh[2][262144];          // weight hi: [0]=qkv_w, [1]=proj_w
__device__ __nv_bfloat16 g_wl[2][262144];          // weight lo
__device__ float g_bias[32768];                    // bias_full[h][i][j]

// ---------------------------------------------------------------------------
// helpers
// ---------------------------------------------------------------------------
__device__ __forceinline__ uint32_t smem_u32(const void* p) {
    uint32_t a;
    asm("{ .reg .u64 t; cvta.to.shared.u64 t, %1; cvt.u32.u64 %0, t; }"
        : "=r"(a) : "l"(p));
    return a;
}

__device__ __forceinline__ void ldsm_x4(uint32_t* d, uint32_t addr) {
    asm volatile("ldmatrix.sync.aligned.m8n8.x4.shared.b16 {%0,%1,%2,%3}, [%4];"
        : "=r"(d[0]), "=r"(d[1]), "=r"(d[2]), "=r"(d[3]) : "r"(addr));
}

__device__ __forceinline__ void ldsm_x4_t(uint32_t* d, uint32_t addr) {
    asm volatile("ldmatrix.sync.aligned.m8n8.x4.trans.shared.b16 {%0,%1,%2,%3}, [%4];"
        : "=r"(d[0]), "=r"(d[1]), "=r"(d[2]), "=r"(d[3]) : "r"(addr));
}

__device__ __forceinline__ void mma16816(float* c, const uint32_t* a,
                                         uint32_t b0, uint32_t b1) {
    asm volatile("mma.sync.aligned.m16n8k16.row.col.f32.bf16.bf16.f32 "
        "{%0,%1,%2,%3}, {%4,%5,%6,%7}, {%8,%9}, {%0,%1,%2,%3};"
        : "+f"(c[0]), "+f"(c[1]), "+f"(c[2]), "+f"(c[3])
        : "r"(a[0]), "r"(a[1]), "r"(a[2]), "r"(a[3]), "r"(b0), "r"(b1));
}

__device__ __forceinline__ void cp16(uint32_t smem, const void* g) {
    asm volatile("cp.async.cg.shared.global [%0], [%1], 16;"
        :: "r"(smem), "l"(g));
}
#define CP_COMMIT() asm volatile("cp.async.commit_group;" ::: "memory")
#define CP_WAIT(n)  asm volatile("cp.async.wait_group %0;" :: "n"(n) : "memory")

__device__ __forceinline__ uint32_t pack_bf2(float a, float b) {
    __nv_bfloat162 t = __floats2bfloat162_rn(a, b);
    return *reinterpret_cast<uint32_t*>(&t);
}

__device__ __forceinline__ void split_f4(float4 v, uint2* hi, uint2* lo) {
    __nv_bfloat16 hx = __float2bfloat16(v.x), hy = __float2bfloat16(v.y);
    __nv_bfloat16 hz = __float2bfloat16(v.z), hw = __float2bfloat16(v.w);
    float lx = v.x - __bfloat162float(hx), ly = v.y - __bfloat162float(hy);
    float lz = v.z - __bfloat162float(hz), lw = v.w - __bfloat162float(hw);
    *hi = make_uint2(pack_bf2(__bfloat162float(hx), __bfloat162float(hy)),
                     pack_bf2(__bfloat162float(hz), __bfloat162float(hw)));
    *lo = make_uint2(pack_bf2(lx, ly), pack_bf2(lz, lw));
}

// ---------------------------------------------------------------------------
// converters
// ---------------------------------------------------------------------------
__global__ void conv_w_kernel(const float* __restrict__ w0, const float* __restrict__ w1)
{
    int which = blockIdx.y;
    const float* src = which ? w1 : w0;
    int i = blockIdx.x * 256 + threadIdx.x;
    float4 v = ((const float4*)src)[i];
    uint2 h, l;
    split_f4(v, &h, &l);
    ((uint2*)g_wh[which])[i] = h;
    ((uint2*)g_wl[which])[i] = l;
}

__global__ void conv_x_kernel(const float* __restrict__ x)
{
    int i = blockIdx.x * 256 + threadIdx.x;          // 0..33554431 float4s
    float4 v = __ldcs(((const float4*)x) + i);
    uint2 h, l;
    split_f4(v, &h, &l);
    ((uint2*)g_xh)[i] = h;
    ((uint2*)g_xl)[i] = l;
}

__global__ void bias_kernel(const float* __restrict__ table, const int* __restrict__ rpi)
{
    int idx = blockIdx.x * 256 + threadIdx.x;
    int h = idx >> 12, ij = idx & 4095;
    g_bias[idx] = table[rpi[ij] * 8 + h];
}

// ---------------------------------------------------------------------------
// cp.async 3-stage split-bf16 GEMM:  C[M,512] = A * W^T + bias
// All operands pre-split bf16 hi/lo in global. CTA tile 128x128, K-chunk 32.
// MODE 0: write q split (Ch/Cl) at [B,H,N,64] with *0.125
// MODE 1: write fp32 row-major [M,512] to C
// ---------------------------------------------------------------------------
#define RP     80
#define AH_OFF 0
#define AL_OFF 10240
#define WH_OFF 20480
#define WL_OFF 30720
#define G_STAGE 40960
#define G_SMEM  (3 * G_STAGE)          // 122880

template <int MODE>
__global__ void __launch_bounds__(256) gemm_cp(
    const __nv_bfloat16* __restrict__ Ah, const __nv_bfloat16* __restrict__ Al,
    const __nv_bfloat16* __restrict__ Wh, const __nv_bfloat16* __restrict__ Wl,
    const float* __restrict__ bias, float* __restrict__ C,
    __nv_bfloat16* __restrict__ Ch, __nv_bfloat16* __restrict__ Cl)
{
    extern __shared__ char smem[];
    const uint32_t sbase = smem_u32(smem);
    const int tid  = threadIdx.x;
    const int wid  = tid >> 5;
    const int lane = tid & 31;
    const int wr   = wid & 3;
    const int wn   = wid >> 2;
    const int n0   = blockIdx.x;
    const int m0   = blockIdx.y;

    // per-thread load coords: 512 16B-chunks per buffer, 2 per thread
    const int r_  = tid >> 2;            // +64 for second
    const int c_  = tid & 3;

    const int L = lane;
    const uint32_t a_lrow = (L & 7) + ((L >> 3) & 1) * 8;
    const uint32_t a_lcol = ((L >> 4) & 1) * 16;
    const uint32_t b_lrow = (L & 7) + ((L >> 4) & 1) * 8;
    const uint32_t b_lcol = ((L >> 3) & 1) * 16;

    float acc[2][8][4];
#pragma unroll
    for (int mt = 0; mt < 2; mt++)
#pragma unroll
        for (int nt = 0; nt < 8; nt++)
#pragma unroll
            for (int q = 0; q < 4; q++) acc[mt][nt][q] = 0.f;

#define ISSUE(kt, buf)                                                         \
    {                                                                          \
        const uint32_t sg = sbase + (buf) * G_STAGE;                           \
        _Pragma("unroll")                                                      \
        for (int i = 0; i < 2; i++) {                                          \
            int r = r_ + i * 64;                                               \
            uint32_t so = r * RP + c_ * 16;                                    \
            size_t ga = (size_t)(m0 * 128 + r) * 512 + (kt) * 32 + c_ * 8;     \
            size_t gb = (size_t)(n0 * 128 + r) * 512 + (kt) * 32 + c_ * 8;     \
            cp16(sg + AH_OFF + so, Ah + ga);                                   \
            cp16(sg + AL_OFF + so, Al + ga);                                   \
            cp16(sg + WH_OFF + so, Wh + gb);                                   \
            cp16(sg + WL_OFF + so, Wl + gb);                                   \
        }                                                                      \
        CP_COMMIT();                                                           \
    }

    ISSUE(0, 0);
    ISSUE(1, 1);

    for (int kt = 0; kt < 16; kt++) {
        if (kt < 15) { CP_WAIT(1); } else { CP_WAIT(0); }
        __syncthreads();
        if (kt + 2 < 16) ISSUE(kt + 2, (kt + 2) % 3);

        const uint32_t stg = sbase + (kt % 3) * G_STAGE;
#pragma unroll
        for (int s = 0; s < 2; s++) {
            uint32_t ah[2][4], al[2][4];
#pragma unroll
            for (int mt = 0; mt < 2; mt++) {
                uint32_t ro = (wr * 32 + mt * 16 + a_lrow) * RP + s * 32 + a_lcol;
                ldsm_x4(ah[mt], stg + AH_OFF + ro);
                ldsm_x4(al[mt], stg + AL_OFF + ro);
            }
#pragma unroll
            for (int g = 0; g < 4; g++) {
                uint32_t bh[4], bl[4];
                uint32_t ro = (wn * 64 + g * 16 + b_lrow) * RP + s * 32 + b_lcol;
                ldsm_x4(bh, stg + WH_OFF + ro);
                ldsm_x4(bl, stg + WL_OFF + ro);
#pragma unroll
                for (int mt = 0; mt < 2; mt++) {
                    mma16816(acc[mt][2 * g],     ah[mt], bh[0], bh[1]);
                    mma16816(acc[mt][2 * g + 1], ah[mt], bh[2], bh[3]);
                    mma16816(acc[mt][2 * g],     al[mt], bh[0], bh[1]);
                    mma16816(acc[mt][2 * g + 1], al[mt], bh[2], bh[3]);
                    mma16816(acc[mt][2 * g],     ah[mt], bl[0], bl[1]);
                    mma16816(acc[mt][2 * g + 1], ah[mt], bl[2], bl[3]);
                }
            }
        }
    }
#undef ISSUE

    const int g_  = lane >> 2;
    const int tig = lane & 3;
#pragma unroll
    for (int mt = 0; mt < 2; mt++) {
        const int mbase = m0 * 128 + wr * 32 + mt * 16 + g_;
#pragma unroll
        for (int nt = 0; nt < 8; nt++) {
            const int j = n0 * 128 + wn * 64 + nt * 8 + tig * 2;
            const float bx = __ldg(bias + j), by = __ldg(bias + j + 1);
#pragma unroll
            for (int half = 0; half < 2; half++) {
                const int m = mbase + half * 8;
                float ox = acc[mt][nt][2 * half]     + bx;
                float oy = acc[mt][nt][2 * half + 1] + by;
                if (MODE == 0) {
                    ox *= 0.125f; oy *= 0.125f;
                    int b_i = m >> 6, n_i = m & 63;
                    int h_i = j >> 6, d_i = j & 63;
                    size_t o = (((size_t)(b_i * 8 + h_i)) << 12) + (n_i << 6) + d_i;
                    __nv_bfloat16 hx = __float2bfloat16(ox);
                    __nv_bfloat16 hy = __float2bfloat16(oy);
                    *(uint32_t*)(Ch + o) =
                        pack_bf2(__bfloat162float(hx), __bfloat162float(hy));
                    *(uint32_t*)(Cl + o) =
                        pack_bf2(ox - __bfloat162float(hx), oy - __bfloat162float(hy));
                } else {
                    *(float2*)(C + (size_t)m * 512 + j) = make_float2(ox, oy);
                }
            }
        }
    }
}

// ---------------------------------------------------------------------------
// Attention via mma.sync split-bf16. One block per (b, h), 128 threads.
// Writes attn out pre-split bf16 hi/lo; fuses p_k/p_v pass-through.
// ---------------------------------------------------------------------------
#define AP 144
#define QH_O 0
#define QL_O 9216
#define KH_O 18432
#define KL_O 27648
#define VH_O 36864
#define VL_O 46080
#define A_SMEM 55296

__global__ void __launch_bounds__(128) attn_mma(
    const float* __restrict__ pk, const float* __restrict__ pv,
    const float* __restrict__ mask,
    float* __restrict__ out_k, float* __restrict__ out_v)
{
    extern __shared__ char smem[];
    const uint32_t sb = smem_u32(smem);
    const int tid = threadIdx.x;
    const int wid = tid >> 5;
    const int lane = tid & 31;
    const int bh = blockIdx.x;
    const int b = bh >> 3, h = bh & 7;
    const int w = b & 255;

    const uint2* qhg = (const uint2*)(g_qh + (size_t)bh * 4096);
    const uint2* qlg = (const uint2*)(g_ql + (size_t)bh * 4096);
    const float4* kg = (const float4*)(pk + (size_t)bh * 4096);
    const float4* vg = (const float4*)(pv + (size_t)bh * 4096);
    float4* ok = (float4*)(out_k + (size_t)bh * 4096);
    float4* ov = (float4*)(out_v + (size_t)bh * 4096);

#pragma unroll
    for (int i = 0; i < 8; i++) {
        int idx = tid + i * 128;
        int r = idx >> 4, c = idx & 15;
        uint32_t off = r * AP + c * 8;
        *(uint2*)(smem + QH_O + off) = __ldcs(qhg + idx);
        *(uint2*)(smem + QL_O + off) = __ldcs(qlg + idx);
        uint2 hi, lo;
        float4 k4 = __ldcs(kg + idx);
        __stcs(ok + idx, k4);
        split_f4(k4, &hi, &lo);
        *(uint2*)(smem + KH_O + off) = hi;
        *(uint2*)(smem + KL_O + off) = lo;
        float4 v4 = __ldcs(vg + idx);
        __stcs(ov + idx, v4);
        split_f4(v4, &hi, &lo);
        *(uint2*)(smem + VH_O + off) = hi;
        *(uint2*)(smem + VL_O + off) = lo;
    }
    __syncthreads();

    const uint32_t aQ = sb + QH_O + (wid * 16 + (lane & 15)) * AP + ((lane >> 4) << 4);
    const uint32_t aK = sb + KH_O + ((lane & 7) + ((lane >> 4) << 3)) * AP
                                  + (((lane >> 3) & 1) << 4);
    const uint32_t aV = sb + VH_O + ((lane & 7) + (((lane >> 3) & 1) << 3)) * AP
                                  + ((lane >> 4) << 4);

    float sacc[8][4];
#pragma unroll
    for (int nt = 0; nt < 8; nt++)
#pragma unroll
        for (int q = 0; q < 4; q++) sacc[nt][q] = 0.f;

#pragma unroll
    for (int ks = 0; ks < 4; ks++) {
        uint32_t ahf[4], alf[4];
        ldsm_x4(ahf, aQ + ks * 32);
        ldsm_x4(alf, aQ + (QL_O - QH_O) + ks * 32);
#pragma unroll
        for (int jb = 0; jb < 4; jb++) {
            uint32_t kh[4], kl[4];
            uint32_t ro = jb * 16 * AP + ks * 32;
            ldsm_x4(kh, aK + ro);
            ldsm_x4(kl, aK + (KL_O - KH_O) + ro);
            mma16816(sacc[2 * jb],     ahf, kh[0], kh[1]);
            mma16816(sacc[2 * jb + 1], ahf, kh[2], kh[3]);
            mma16816(sacc[2 * jb],     alf, kh[0], kh[1]);
            mma16816(sacc[2 * jb + 1], alf, kh[2], kh[3]);
            mma16816(sacc[2 * jb],     ahf, kl[0], kl[1]);
            mma16816(sacc[2 * jb + 1], ahf, kl[2], kl[3]);
        }
    }

    const int g_ = lane >> 2, t4 = lane & 3;
    const int i0 = wid * 16 + g_;
    const int i1 = i0 + 8;
    const float* mrow0 = mask + (size_t)w * 4096 + i0 * 64;
    const float* mrow1 = mask + (size_t)w * 4096 + i1 * 64;
    const float* brow0 = g_bias + h * 4096 + i0 * 64;
    const float* brow1 = g_bias + h * 4096 + i1 * 64;

#pragma unroll
    for (int nt = 0; nt < 8; nt++) {
        int j = nt * 8 + t4 * 2;
        float2 m0 = *(const float2*)(mrow0 + j);
        float2 b0 = *(const float2*)(brow0 + j);
        float2 m1 = *(const float2*)(mrow1 + j);
        float2 b1 = *(const float2*)(brow1 + j);
        sacc[nt][0] += m0.x + b0.x;
        sacc[nt][1] += m0.y + b0.y;
        sacc[nt][2] += m1.x + b1.x;
        sacc[nt][3] += m1.y + b1.y;
    }

    float mx0 = -1e30f, mx1 = -1e30f;
#pragma unroll
    for (int nt = 0; nt < 8; nt++) {
        mx0 = fmaxf(mx0, fmaxf(sacc[nt][0], sacc[nt][1]));
        mx1 = fmaxf(mx1, fmaxf(sacc[nt][2], sacc[nt][3]));
    }
    mx0 = fmaxf(mx0, __shfl_xor_sync(0xffffffffu, mx0, 1));
    mx0 = fmaxf(mx0, __shfl_xor_sync(0xffffffffu, mx0, 2));
    mx1 = fmaxf(mx1, __shfl_xor_sync(0xffffffffu, mx1, 1));
    mx1 = fmaxf(mx1, __shfl_xor_sync(0xffffffffu, mx1, 2));

    float s0 = 0.f, s1 = 0.f;
#pragma unroll
    for (int nt = 0; nt < 8; nt++) {
        sacc[nt][0] = __expf(sacc[nt][0] - mx0);
        sacc[nt][1] = __expf(sacc[nt][1] - mx0);
        sacc[nt][2] = __expf(sacc[nt][2] - mx1);
        sacc[nt][3] = __expf(sacc[nt][3] - mx1);
        s0 += sacc[nt][0] + sacc[nt][1];
        s1 += sacc[nt][2] + sacc[nt][3];
    }
    s0 += __shfl_xor_sync(0xffffffffu, s0, 1);
    s0 += __shfl_xor_sync(0xffffffffu, s0, 2);
    s1 += __shfl_xor_sync(0xffffffffu, s1, 1);
    s1 += __shfl_xor_sync(0xffffffffu, s1, 2);
    const float inv0 = 1.0f / s0, inv1 = 1.0f / s1;

    uint32_t phi0[8], plo0[8], phi1[8], plo1[8];
#pragma unroll
    for (int nt = 0; nt < 8; nt++) {
        float p0 = sacc[nt][0] * inv0, p1 = sacc[nt][1] * inv0;
        float p2 = sacc[nt][2] * inv1, p3 = sacc[nt][3] * inv1;
        __nv_bfloat16 h0 = __float2bfloat16(p0), h1 = __float2bfloat16(p1);
        __nv_bfloat16 h2 = __float2bfloat16(p2), h3 = __float2bfloat16(p3);
        phi0[nt] = pack_bf2(__bfloat162float(h0), __bfloat162float(h1));
        phi1[nt] = pack_bf2(__bfloat162float(h2), __bfloat162float(h3));
        plo0[nt] = pack_bf2(p0 - __bfloat162float(h0), p1 - __bfloat162float(h1));
        plo1[nt] = pack_bf2(p2 - __bfloat162float(h2), p3 - __bfloat162float(h3));
    }

    float oacc[8][4];
#pragma unroll
    for (int nt = 0; nt < 8; nt++)
#pragma unroll
        for (int q = 0; q < 4; q++) oacc[nt][q] = 0.f;

#pragma unroll
    for (int ks = 0; ks < 4; ks++) {
        uint32_t pa[4] = {phi0[2 * ks], phi1[2 * ks], phi0[2 * ks + 1], phi1[2 * ks + 1]};
        uint32_t pb[4] = {plo0[2 * ks], plo1[2 * ks], plo0[2 * ks + 1], plo1[2 * ks + 1]};
#pragma unroll
        for (int db = 0; db < 4; db++) {
            uint32_t vh[4], vl[4];
            uint32_t ro = ks * 16 * AP + db * 32;
            ldsm_x4_t(vh, aV + ro);
            ldsm_x4_t(vl, aV + (VL_O - VH_O) + ro);
            mma16816(oacc[2 * db],     pa, vh[0], vh[1]);
            mma16816(oacc[2 * db + 1], pa, vh[2], vh[3]);
            mma16816(oacc[2 * db],     pb, vh[0], vh[1]);
            mma16816(oacc[2 * db + 1], pb, vh[2], vh[3]);
            mma16816(oacc[2 * db],     pa, vl[0], vl[1]);
            mma16816(oacc[2 * db + 1], pa, vl[2], vl[3]);
        }
    }

    // write attn out pre-split bf16 hi/lo
    const size_t o0 = ((size_t)(b * 64 + i0)) * 512 + h * 64;
    const size_t o1 = ((size_t)(b * 64 + i1)) * 512 + h * 64;
#pragma unroll
    for (int nt = 0; nt < 8; nt++) {
        int d = nt * 8 + t4 * 2;
        float a0 = oacc[nt][0], a1 = oacc[nt][1];
        float a2 = oacc[nt][2], a3 = oacc[nt][3];
        __nv_bfloat16 h0 = __float2bfloat16(a0), h1 = __float2bfloat16(a1);
        __nv_bfloat16 h2 = __float2bfloat16(a2), h3 = __float2bfloat16(a3);
        *(uint32_t*)(g_aoh + o0 + d) = pack_bf2(__bfloat162float(h0), __bfloat162float(h1));
        *(uint32_t*)(g_aol + o0 + d) = pack_bf2(a0 - __bfloat162float(h0), a1 - __bfloat162float(h1));
        *(uint32_t*)(g_aoh + o1 + d) = pack_bf2(__bfloat162float(h2), __bfloat162float(h3));
        *(uint32_t*)(g_aol + o1 + d) = pack_bf2(a2 - __bfloat162float(h2), a3 - __bfloat162float(h3));
    }
}

// ---------------------------------------------------------------------------
extern "C" void kernel_launch(void* const* d_in, const int* in_sizes, int n_in,
                              void* d_out, int out_size)
{
    const float* x      = (const float*)d_in[0];
    const float* pk     = (const float*)d_in[1];
    const float* pv     = (const float*)d_in[2];
    const float* mask   = (const float*)d_in[3];
    const float* table  = (const float*)d_in[4];
    const int*   rpi    = (const int*)d_in[5];
    const float* qkv_b  = (const float*)d_in[7];
    const float* proj_b = (const float*)d_in[9];
    const float* qkv_w  = (const float*)d_in[6];
    const float* proj_w = (const float*)d_in[8];
    float* out = (float*)d_out;

    __nv_bfloat16 *xh, *xl, *qh, *ql, *aoh, *aol, *whp, *wlp;
    cudaGetSymbolAddress((void**)&xh,  g_xh);
    cudaGetSymbolAddress((void**)&xl,  g_xl);
    cudaGetSymbolAddress((void**)&qh,  g_qh);
    cudaGetSymbolAddress((void**)&ql,  g_ql);
    cudaGetSymbolAddress((void**)&aoh, g_aoh);
    cudaGetSymbolAddress((void**)&aol, g_aol);
    cudaGetSymbolAddress((void**)&whp, g_wh);
    cudaGetSymbolAddress((void**)&wlp, g_wl);

    static bool attr_set = false;
    if (!attr_set) {
        cudaFuncSetAttribute(gemm_cp<0>, cudaFuncAttributeMaxDynamicSharedMemorySize, G_SMEM);
        cudaFuncSetAttribute(gemm_cp<1>, cudaFuncAttributeMaxDynamicSharedMemorySize, G_SMEM);
        cudaFuncSetAttribute(attn_mma,   cudaFuncAttributeMaxDynamicSharedMemorySize, A_SMEM);
        attr_set = true;
    }

    conv_w_kernel<<<dim3(256, 2), 256>>>(qkv_w, proj_w);
    bias_kernel<<<128, 256>>>(table, rpi);
    conv_x_kernel<<<131072, 256>>>(x);

    dim3 ggrid(4, 2048);   // N/128 x M/128
    gemm_cp<0><<<ggrid, 256, G_SMEM>>>(xh, xl, whp, wlp, qkv_b,
                                       nullptr, qh, ql);

    attn_mma<<<32768, 128, A_SMEM>>>(pk, pv, mask, out + (size_t)PKE,
                                     out + (size_t)2 * PKE);

    gemm_cp<1><<<ggrid, 256, G_SMEM>>>(aoh, aol, whp + 262144, wlp + 262144, proj_b,
                                       out, nullptr, nullptr);
}

// round 8
// speedup vs baseline: 1.2549x; 1.2549x over previous
#include <cuda_runtime.h>
#include <cuda_bf16.h>
#include <cstdint>

#define PKE 134217728   // 4096*8*64*64

// Scratch (__device__ globals; allocation-free rule)
__device__ __nv_bfloat16 g_xh[PKE], g_xl[PKE];     // x split
__device__ __nv_bfloat16 g_qh[PKE], g_ql[PKE];     // q split, [B,H,N,64], pre-scaled
__device__ __nv_bfloat16 g_aoh[PKE], g_aol[PKE];   // attn out split, [B*N,512]
__device__ __nv_bfloat16 g_wh[2][262144];          // weight hi: [0]=qkv_w, [1]=proj_w
__device__ __nv_bfloat16 g_wl[2][262144];          // weight lo
__device__ float g_bias[32768];                    // bias_full[h][i][j]

// ---------------------------------------------------------------------------
// helpers
// ---------------------------------------------------------------------------
__device__ __forceinline__ uint32_t smem_u32(const void* p) {
    uint32_t a;
    asm("{ .reg .u64 t; cvta.to.shared.u64 t, %1; cvt.u32.u64 %0, t; }"
        : "=r"(a) : "l"(p));
    return a;
}

__device__ __forceinline__ void ldsm_x4(uint32_t* d, uint32_t addr) {
    asm volatile("ldmatrix.sync.aligned.m8n8.x4.shared.b16 {%0,%1,%2,%3}, [%4];"
        : "=r"(d[0]), "=r"(d[1]), "=r"(d[2]), "=r"(d[3]) : "r"(addr));
}

__device__ __forceinline__ void ldsm_x4_t(uint32_t* d, uint32_t addr) {
    asm volatile("ldmatrix.sync.aligned.m8n8.x4.trans.shared.b16 {%0,%1,%2,%3}, [%4];"
        : "=r"(d[0]), "=r"(d[1]), "=r"(d[2]), "=r"(d[3]) : "r"(addr));
}

__device__ __forceinline__ void mma16816(float* c, const uint32_t* a,
                                         uint32_t b0, uint32_t b1) {
    asm volatile("mma.sync.aligned.m16n8k16.row.col.f32.bf16.bf16.f32 "
        "{%0,%1,%2,%3}, {%4,%5,%6,%7}, {%8,%9}, {%0,%1,%2,%3};"
        : "+f"(c[0]), "+f"(c[1]), "+f"(c[2]), "+f"(c[3])
        : "r"(a[0]), "r"(a[1]), "r"(a[2]), "r"(a[3]), "r"(b0), "r"(b1));
}

__device__ __forceinline__ void cp16(uint32_t smem, const void* g) {
    asm volatile("cp.async.cg.shared.global [%0], [%1], 16;"
        :: "r"(smem), "l"(g));
}
#define CP_COMMIT() asm volatile("cp.async.commit_group;" ::: "memory")
#define CP_WAIT(n)  asm volatile("cp.async.wait_group %0;" :: "n"(n) : "memory")

__device__ __forceinline__ uint32_t pack_bf2(float a, float b) {
    __nv_bfloat162 t = __floats2bfloat162_rn(a, b);
    return *reinterpret_cast<uint32_t*>(&t);
}

__device__ __forceinline__ void split_f4(float4 v, uint2* hi, uint2* lo) {
    __nv_bfloat16 hx = __float2bfloat16(v.x), hy = __float2bfloat16(v.y);
    __nv_bfloat16 hz = __float2bfloat16(v.z), hw = __float2bfloat16(v.w);
    float lx = v.x - __bfloat162float(hx), ly = v.y - __bfloat162float(hy);
    float lz = v.z - __bfloat162float(hz), lw = v.w - __bfloat162float(hw);
    *hi = make_uint2(pack_bf2(__bfloat162float(hx), __bfloat162float(hy)),
                     pack_bf2(__bfloat162float(hz), __bfloat162float(hw)));
    *lo = make_uint2(pack_bf2(lx, ly), pack_bf2(lz, lw));
}

// ---------------------------------------------------------------------------
// converters
// ---------------------------------------------------------------------------
__global__ void conv_w_kernel(const float* __restrict__ w0, const float* __restrict__ w1)
{
    int which = blockIdx.y;
    const float* src = which ? w1 : w0;
    int i = blockIdx.x * 256 + threadIdx.x;
    float4 v = ((const float4*)src)[i];
    uint2 h, l;
    split_f4(v, &h, &l);
    ((uint2*)g_wh[which])[i] = h;
    ((uint2*)g_wl[which])[i] = l;
}

__global__ void conv_x_kernel(const float* __restrict__ x)
{
    int i = blockIdx.x * 256 + threadIdx.x;
    float4 v = __ldcs(((const float4*)x) + i);
    uint2 h, l;
    split_f4(v, &h, &l);
    ((uint2*)g_xh)[i] = h;
    ((uint2*)g_xl)[i] = l;
}

__global__ void bias_kernel(const float* __restrict__ table, const int* __restrict__ rpi)
{
    int idx = blockIdx.x * 256 + threadIdx.x;
    int h = idx >> 12, ij = idx & 4095;
    g_bias[idx] = table[rpi[ij] * 8 + h];
}

// ---------------------------------------------------------------------------
// cp.async 3-stage split-bf16 GEMM, 64B-pitch XOR-swizzled smem, 2 CTAs/SM.
// C[M,512] = A * W^T + bias.  CTA tile 128x128, K-chunk 32.
// smem layout per stage: Ah | Al | Wh | Wl, each 128 rows x 64 B.
// swizzle: 16B-chunk' = chunk ^ ((row >> 1) & 3)
// MODE 0: write q split (Ch/Cl) at [B,H,N,64] with *0.125
// MODE 1: write fp32 row-major [M,512] to C
// ---------------------------------------------------------------------------
#define AH_OFF 0
#define AL_OFF 8192
#define WH_OFF 16384
#define WL_OFF 24576
#define G_STAGE 32768
#define G_SMEM  (3 * G_STAGE)          // 98304

template <int MODE>
__global__ void __launch_bounds__(256, 2) gemm_cp(
    const __nv_bfloat16* __restrict__ Ah, const __nv_bfloat16* __restrict__ Al,
    const __nv_bfloat16* __restrict__ Wh, const __nv_bfloat16* __restrict__ Wl,
    const float* __restrict__ bias, float* __restrict__ C,
    __nv_bfloat16* __restrict__ Ch, __nv_bfloat16* __restrict__ Cl)
{
    extern __shared__ char smem[];
    const uint32_t sbase = smem_u32(smem);
    const int tid  = threadIdx.x;
    const int wid  = tid >> 5;
    const int lane = tid & 31;
    const int wr   = wid & 3;
    const int wn   = wid >> 2;
    const int n0   = blockIdx.x;
    const int m0   = blockIdx.y;

    // cp.async coords: 2 iters x (row r_, 16B chunk c_) covering 128x64B
    const int r_  = tid >> 2;
    const int c_  = tid & 3;
    const uint32_t st_off0 = r_ * 64 + ((c_ ^ ((r_ >> 1) & 3)) << 4);
    const int r2_ = r_ + 64;
    const uint32_t st_off1 = r2_ * 64 + ((c_ ^ ((r2_ >> 1) & 3)) << 4);

    // ldmatrix lane geometry
    const int L = lane;
    const uint32_t a_lrow = (L & 7) + ((L >> 3) & 1) * 8;       // 0..15
    const uint32_t b_lrow = (L & 7) + ((L >> 4) & 1) * 8;       // 0..15
    const uint32_t a_swz  = (a_lrow >> 1) & 3;
    const uint32_t b_swz  = (b_lrow >> 1) & 3;
    // swizzled 16B-chunk byte offsets per K-slice s
    uint32_t a_col[2], b_col[2];
#pragma unroll
    for (int s = 0; s < 2; s++) {
        a_col[s] = (((uint32_t)(2 * s + (L >> 4)) ^ a_swz) << 4);
        b_col[s] = (((uint32_t)(2 * s + ((L >> 3) & 1)) ^ b_swz) << 4);
    }
    // row base offsets (bytes)
    uint32_t a_row[2], b_row[4];
#pragma unroll
    for (int mt = 0; mt < 2; mt++) a_row[mt] = (wr * 32 + mt * 16 + a_lrow) * 64;
#pragma unroll
    for (int g = 0; g < 4; g++)    b_row[g]  = (wn * 64 + g * 16 + b_lrow) * 64;

    float acc[2][8][4];
#pragma unroll
    for (int mt = 0; mt < 2; mt++)
#pragma unroll
        for (int nt = 0; nt < 8; nt++)
#pragma unroll
            for (int q = 0; q < 4; q++) acc[mt][nt][q] = 0.f;

#define ISSUE(kt, buf)                                                         \
    {                                                                          \
        const uint32_t sg = sbase + (buf) * G_STAGE;                           \
        size_t ga0 = (size_t)(m0 * 128 + r_) * 512 + (kt) * 32 + c_ * 8;       \
        size_t gb0 = (size_t)(n0 * 128 + r_) * 512 + (kt) * 32 + c_ * 8;       \
        cp16(sg + AH_OFF + st_off0, Ah + ga0);                                 \
        cp16(sg + AL_OFF + st_off0, Al + ga0);                                 \
        cp16(sg + WH_OFF + st_off0, Wh + gb0);                                 \
        cp16(sg + WL_OFF + st_off0, Wl + gb0);                                 \
        size_t ga1 = ga0 + (size_t)64 * 512;                                   \
        size_t gb1 = gb0 + (size_t)64 * 512;                                   \
        cp16(sg + AH_OFF + st_off1, Ah + ga1);                                 \
        cp16(sg + AL_OFF + st_off1, Al + ga1);                                 \
        cp16(sg + WH_OFF + st_off1, Wh + gb1);                                 \
        cp16(sg + WL_OFF + st_off1, Wl + gb1);                                 \
        CP_COMMIT();                                                           \
    }

    ISSUE(0, 0);
    ISSUE(1, 1);

    for (int kt = 0; kt < 16; kt++) {
        if (kt < 15) { CP_WAIT(1); } else { CP_WAIT(0); }
        __syncthreads();
        if (kt + 2 < 16) ISSUE(kt + 2, (kt + 2) % 3);

        const uint32_t stg = sbase + (kt % 3) * G_STAGE;
#pragma unroll
        for (int s = 0; s < 2; s++) {
            uint32_t ah[2][4], al[2][4];
#pragma unroll
            for (int mt = 0; mt < 2; mt++) {
                ldsm_x4(ah[mt], stg + AH_OFF + a_row[mt] + a_col[s]);
                ldsm_x4(al[mt], stg + AL_OFF + a_row[mt] + a_col[s]);
            }
#pragma unroll
            for (int g = 0; g < 4; g++) {
                uint32_t bh[4], bl[4];
                ldsm_x4(bh, stg + WH_OFF + b_row[g] + b_col[s]);
                ldsm_x4(bl, stg + WL_OFF + b_row[g] + b_col[s]);
#pragma unroll
                for (int mt = 0; mt < 2; mt++) {
                    mma16816(acc[mt][2 * g],     ah[mt], bh[0], bh[1]);
                    mma16816(acc[mt][2 * g + 1], ah[mt], bh[2], bh[3]);
                    mma16816(acc[mt][2 * g],     al[mt], bh[0], bh[1]);
                    mma16816(acc[mt][2 * g + 1], al[mt], bh[2], bh[3]);
                    mma16816(acc[mt][2 * g],     ah[mt], bl[0], bl[1]);
                    mma16816(acc[mt][2 * g + 1], ah[mt], bl[2], bl[3]);
                }
            }
        }
    }
#undef ISSUE

    const int g_  = lane >> 2;
    const int tig = lane & 3;
#pragma unroll
    for (int mt = 0; mt < 2; mt++) {
        const int mbase = m0 * 128 + wr * 32 + mt * 16 + g_;
#pragma unroll
        for (int nt = 0; nt < 8; nt++) {
            const int j = n0 * 128 + wn * 64 + nt * 8 + tig * 2;
            const float bx = __ldg(bias + j), by = __ldg(bias + j + 1);
#pragma unroll
            for (int half = 0; half < 2; half++) {
                const int m = mbase + half * 8;
                float ox = acc[mt][nt][2 * half]     + bx;
                float oy = acc[mt][nt][2 * half + 1] + by;
                if (MODE == 0) {
                    ox *= 0.125f; oy *= 0.125f;
                    int b_i = m >> 6, n_i = m & 63;
                    int h_i = j >> 6, d_i = j & 63;
                    size_t o = (((size_t)(b_i * 8 + h_i)) << 12) + (n_i << 6) + d_i;
                    __nv_bfloat16 hx = __float2bfloat16(ox);
                    __nv_bfloat16 hy = __float2bfloat16(oy);
                    *(uint32_t*)(Ch + o) =
                        pack_bf2(__bfloat162float(hx), __bfloat162float(hy));
                    *(uint32_t*)(Cl + o) =
                        pack_bf2(ox - __bfloat162float(hx), oy - __bfloat162float(hy));
                } else {
                    *(float2*)(C + (size_t)m * 512 + j) = make_float2(ox, oy);
                }
            }
        }
    }
}

// ---------------------------------------------------------------------------
// Attention via mma.sync split-bf16 (unchanged from R5 passing version).
// ---------------------------------------------------------------------------
#define AP 144
#define QH_O 0
#define QL_O 9216
#define KH_O 18432
#define KL_O 27648
#define VH_O 36864
#define VL_O 46080
#define A_SMEM 55296

__global__ void __launch_bounds__(128) attn_mma(
    const float* __restrict__ pk, const float* __restrict__ pv,
    const float* __restrict__ mask,
    float* __restrict__ out_k, float* __restrict__ out_v)
{
    extern __shared__ char smem[];
    const uint32_t sb = smem_u32(smem);
    const int tid = threadIdx.x;
    const int wid = tid >> 5;
    const int lane = tid & 31;
    const int bh = blockIdx.x;
    const int b = bh >> 3, h = bh & 7;
    const int w = b & 255;

    const uint2* qhg = (const uint2*)(g_qh + (size_t)bh * 4096);
    const uint2* qlg = (const uint2*)(g_ql + (size_t)bh * 4096);
    const float4* kg = (const float4*)(pk + (size_t)bh * 4096);
    const float4* vg = (const float4*)(pv + (size_t)bh * 4096);
    float4* ok = (float4*)(out_k + (size_t)bh * 4096);
    float4* ov = (float4*)(out_v + (size_t)bh * 4096);

#pragma unroll
    for (int i = 0; i < 8; i++) {
        int idx = tid + i * 128;
        int r = idx >> 4, c = idx & 15;
        uint32_t off = r * AP + c * 8;
        *(uint2*)(smem + QH_O + off) = __ldcs(qhg + idx);
        *(uint2*)(smem + QL_O + off) = __ldcs(qlg + idx);
        uint2 hi, lo;
        float4 k4 = __ldcs(kg + idx);
        __stcs(ok + idx, k4);
        split_f4(k4, &hi, &lo);
        *(uint2*)(smem + KH_O + off) = hi;
        *(uint2*)(smem + KL_O + off) = lo;
        float4 v4 = __ldcs(vg + idx);
        __stcs(ov + idx, v4);
        split_f4(v4, &hi, &lo);
        *(uint2*)(smem + VH_O + off) = hi;
        *(uint2*)(smem + VL_O + off) = lo;
    }
    __syncthreads();

    const uint32_t aQ = sb + QH_O + (wid * 16 + (lane & 15)) * AP + ((lane >> 4) << 4);
    const uint32_t aK = sb + KH_O + ((lane & 7) + ((lane >> 4) << 3)) * AP
                                  + (((lane >> 3) & 1) << 4);
    const uint32_t aV = sb + VH_O + ((lane & 7) + (((lane >> 3) & 1) << 3)) * AP
                                  + ((lane >> 4) << 4);

    float sacc[8][4];
#pragma unroll
    for (int nt = 0; nt < 8; nt++)
#pragma unroll
        for (int q = 0; q < 4; q++) sacc[nt][q] = 0.f;

#pragma unroll
    for (int ks = 0; ks < 4; ks++) {
        uint32_t ahf[4], alf[4];
        ldsm_x4(ahf, aQ + ks * 32);
        ldsm_x4(alf, aQ + (QL_O - QH_O) + ks * 32);
#pragma unroll
        for (int jb = 0; jb < 4; jb++) {
            uint32_t kh[4], kl[4];
            uint32_t ro = jb * 16 * AP + ks * 32;
            ldsm_x4(kh, aK + ro);
            ldsm_x4(kl, aK + (KL_O - KH_O) + ro);
            mma16816(sacc[2 * jb],     ahf, kh[0], kh[1]);
            mma16816(sacc[2 * jb + 1], ahf, kh[2], kh[3]);
            mma16816(sacc[2 * jb],     alf, kh[0], kh[1]);
            mma16816(sacc[2 * jb + 1], alf, kh[2], kh[3]);
            mma16816(sacc[2 * jb],     ahf, kl[0], kl[1]);
            mma16816(sacc[2 * jb + 1], ahf, kl[2], kl[3]);
        }
    }

    const int g_ = lane >> 2, t4 = lane & 3;
    const int i0 = wid * 16 + g_;
    const int i1 = i0 + 8;
    const float* mrow0 = mask + (size_t)w * 4096 + i0 * 64;
    const float* mrow1 = mask + (size_t)w * 4096 + i1 * 64;
    const float* brow0 = g_bias + h * 4096 + i0 * 64;
    const float* brow1 = g_bias + h * 4096 + i1 * 64;

#pragma unroll
    for (int nt = 0; nt < 8; nt++) {
        int j = nt * 8 + t4 * 2;
        float2 m0 = *(const float2*)(mrow0 + j);
        float2 b0 = *(const float2*)(brow0 + j);
        float2 m1 = *(const float2*)(mrow1 + j);
        float2 b1 = *(const float2*)(brow1 + j);
        sacc[nt][0] += m0.x + b0.x;
        sacc[nt][1] += m0.y + b0.y;
        sacc[nt][2] += m1.x + b1.x;
        sacc[nt][3] += m1.y + b1.y;
    }

    float mx0 = -1e30f, mx1 = -1e30f;
#pragma unroll
    for (int nt = 0; nt < 8; nt++) {
        mx0 = fmaxf(mx0, fmaxf(sacc[nt][0], sacc[nt][1]));
        mx1 = fmaxf(mx1, fmaxf(sacc[nt][2], sacc[nt][3]));
    }
    mx0 = fmaxf(mx0, __shfl_xor_sync(0xffffffffu, mx0, 1));
    mx0 = fmaxf(mx0, __shfl_xor_sync(0xffffffffu, mx0, 2));
    mx1 = fmaxf(mx1, __shfl_xor_sync(0xffffffffu, mx1, 1));
    mx1 = fmaxf(mx1, __shfl_xor_sync(0xffffffffu, mx1, 2));

    float s0 = 0.f, s1 = 0.f;
#pragma unroll
    for (int nt = 0; nt < 8; nt++) {
        sacc[nt][0] = __expf(sacc[nt][0] - mx0);
        sacc[nt][1] = __expf(sacc[nt][1] - mx0);
        sacc[nt][2] = __expf(sacc[nt][2] - mx1);
        sacc[nt][3] = __expf(sacc[nt][3] - mx1);
        s0 += sacc[nt][0] + sacc[nt][1];
        s1 += sacc[nt][2] + sacc[nt][3];
    }
    s0 += __shfl_xor_sync(0xffffffffu, s0, 1);
    s0 += __shfl_xor_sync(0xffffffffu, s0, 2);
    s1 += __shfl_xor_sync(0xffffffffu, s1, 1);
    s1 += __shfl_xor_sync(0xffffffffu, s1, 2);
    const float inv0 = 1.0f / s0, inv1 = 1.0f / s1;

    uint32_t phi0[8], plo0[8], phi1[8], plo1[8];
#pragma unroll
    for (int nt = 0; nt < 8; nt++) {
        float p0 = sacc[nt][0] * inv0, p1 = sacc[nt][1] * inv0;
        float p2 = sacc[nt][2] * inv1, p3 = sacc[nt][3] * inv1;
        __nv_bfloat16 h0 = __float2bfloat16(p0), h1 = __float2bfloat16(p1);
        __nv_bfloat16 h2 = __float2bfloat16(p2), h3 = __float2bfloat16(p3);
        phi0[nt] = pack_bf2(__bfloat162float(h0), __bfloat162float(h1));
        phi1[nt] = pack_bf2(__bfloat162float(h2), __bfloat162float(h3));
        plo0[nt] = pack_bf2(p0 - __bfloat162float(h0), p1 - __bfloat162float(h1));
        plo1[nt] = pack_bf2(p2 - __bfloat162float(h2), p3 - __bfloat162float(h3));
    }

    float oacc[8][4];
#pragma unroll
    for (int nt = 0; nt < 8; nt++)
#pragma unroll
        for (int q = 0; q < 4; q++) oacc[nt][q] = 0.f;

#pragma unroll
    for (int ks = 0; ks < 4; ks++) {
        uint32_t pa[4] = {phi0[2 * ks], phi1[2 * ks], phi0[2 * ks + 1], phi1[2 * ks + 1]};
        uint32_t pb[4] = {plo0[2 * ks], plo1[2 * ks], plo0[2 * ks + 1], plo1[2 * ks + 1]};
#pragma unroll
        for (int db = 0; db < 4; db++) {
            uint32_t vh[4], vl[4];
            uint32_t ro = ks * 16 * AP + db * 32;
            ldsm_x4_t(vh, aV + ro);
            ldsm_x4_t(vl, aV + (VL_O - VH_O) + ro);
            mma16816(oacc[2 * db],     pa, vh[0], vh[1]);
            mma16816(oacc[2 * db + 1], pa, vh[2], vh[3]);
            mma16816(oacc[2 * db],     pb, vh[0], vh[1]);
            mma16816(oacc[2 * db + 1], pb, vh[2], vh[3]);
            mma16816(oacc[2 * db],     pa, vl[0], vl[1]);
            mma16816(oacc[2 * db + 1], pa, vl[2], vl[3]);
        }
    }

    const size_t o0 = ((size_t)(b * 64 + i0)) * 512 + h * 64;
    const size_t o1 = ((size_t)(b * 64 + i1)) * 512 + h * 64;
#pragma unroll
    for (int nt = 0; nt < 8; nt++) {
        int d = nt * 8 + t4 * 2;
        float a0 = oacc[nt][0], a1 = oacc[nt][1];
        float a2 = oacc[nt][2], a3 = oacc[nt][3];
        __nv_bfloat16 h0 = __float2bfloat16(a0), h1 = __float2bfloat16(a1);
        __nv_bfloat16 h2 = __float2bfloat16(a2), h3 = __float2bfloat16(a3);
        *(uint32_t*)(g_aoh + o0 + d) = pack_bf2(__bfloat162float(h0), __bfloat162float(h1));
        *(uint32_t*)(g_aol + o0 + d) = pack_bf2(a0 - __bfloat162float(h0), a1 - __bfloat162float(h1));
        *(uint32_t*)(g_aoh + o1 + d) = pack_bf2(__bfloat162float(h2), __bfloat162float(h3));
        *(uint32_t*)(g_aol + o1 + d) = pack_bf2(a2 - __bfloat162float(h2), a3 - __bfloat162float(h3));
    }
}

// ---------------------------------------------------------------------------
extern "C" void kernel_launch(void* const* d_in, const int* in_sizes, int n_in,
                              void* d_out, int out_size)
{
    const float* x      = (const float*)d_in[0];
    const float* pk     = (const float*)d_in[1];
    const float* pv     = (const float*)d_in[2];
    const float* mask   = (const float*)d_in[3];
    const float* table  = (const float*)d_in[4];
    const int*   rpi    = (const int*)d_in[5];
    const float* qkv_w  = (const float*)d_in[6];
    const float* qkv_b  = (const float*)d_in[7];
    const float* proj_w = (const float*)d_in[8];
    const float* proj_b = (const float*)d_in[9];
    float* out = (float*)d_out;

    __nv_bfloat16 *xh, *xl, *qh, *ql, *aoh, *aol, *whp, *wlp;
    cudaGetSymbolAddress((void**)&xh,  g_xh);
    cudaGetSymbolAddress((void**)&xl,  g_xl);
    cudaGetSymbolAddress((void**)&qh,  g_qh);
    cudaGetSymbolAddress((void**)&ql,  g_ql);
    cudaGetSymbolAddress((void**)&aoh, g_aoh);
    cudaGetSymbolAddress((void**)&aol, g_aol);
    cudaGetSymbolAddress((void**)&whp, g_wh);
    cudaGetSymbolAddress((void**)&wlp, g_wl);

    static bool attr_set = false;
    if (!attr_set) {
        cudaFuncSetAttribute(gemm_cp<0>, cudaFuncAttributeMaxDynamicSharedMemorySize, G_SMEM);
        cudaFuncSetAttribute(gemm_cp<1>, cudaFuncAttributeMaxDynamicSharedMemorySize, G_SMEM);
        cudaFuncSetAttribute(attn_mma,   cudaFuncAttributeMaxDynamicSharedMemorySize, A_SMEM);
        attr_set = true;
    }

    conv_w_kernel<<<dim3(256, 2), 256>>>(qkv_w, proj_w);
    bias_kernel<<<128, 256>>>(table, rpi);
    conv_x_kernel<<<131072, 256>>>(x);

    dim3 ggrid(4, 2048);   // N/128 x M/128
    gemm_cp<0><<<ggrid, 256, G_SMEM>>>(xh, xl, whp, wlp, qkv_b,
                                       nullptr, qh, ql);

    attn_mma<<<32768, 128, A_SMEM>>>(pk, pv, mask, out + (size_t)PKE,
                                     out + (size_t)2 * PKE);

    gemm_cp<1><<<ggrid, 256, G_SMEM>>>(aoh, aol, whp + 262144, wlp + 262144, proj_b,
                                       out, nullptr, nullptr);
}

// round 9
// speedup vs baseline: 1.3003x; 1.0362x over previous
#include <cuda_runtime.h>
#include <cuda_bf16.h>
#include <cstdint>

#define PKE 134217728   // 4096*8*64*64

// Scratch (__device__ globals; allocation-free rule)
__device__ __nv_bfloat16 g_xh[PKE], g_xl[PKE];     // x split
__device__ __nv_bfloat16 g_qh[PKE], g_ql[PKE];     // q split, [B,H,N,64], pre-scaled
__device__ __nv_bfloat16 g_aoh[PKE], g_aol[PKE];   // attn out split, [B*N,512]
__device__ __nv_bfloat16 g_wh[2][262144];          // weight hi: [0]=qkv_w, [1]=proj_w
__device__ __nv_bfloat16 g_wl[2][262144];          // weight lo
__device__ float g_bias[32768];                    // bias_full[h][i][j]

// ---------------------------------------------------------------------------
// helpers
// ---------------------------------------------------------------------------
__device__ __forceinline__ uint32_t smem_u32(const void* p) {
    uint32_t a;
    asm("{ .reg .u64 t; cvta.to.shared.u64 t, %1; cvt.u32.u64 %0, t; }"
        : "=r"(a) : "l"(p));
    return a;
}

__device__ __forceinline__ void ldsm_x4(uint32_t* d, uint32_t addr) {
    asm volatile("ldmatrix.sync.aligned.m8n8.x4.shared.b16 {%0,%1,%2,%3}, [%4];"
        : "=r"(d[0]), "=r"(d[1]), "=r"(d[2]), "=r"(d[3]) : "r"(addr));
}

__device__ __forceinline__ void ldsm_x4_t(uint32_t* d, uint32_t addr) {
    asm volatile("ldmatrix.sync.aligned.m8n8.x4.trans.shared.b16 {%0,%1,%2,%3}, [%4];"
        : "=r"(d[0]), "=r"(d[1]), "=r"(d[2]), "=r"(d[3]) : "r"(addr));
}

__device__ __forceinline__ void mma16816(float* c, const uint32_t* a,
                                         uint32_t b0, uint32_t b1) {
    asm volatile("mma.sync.aligned.m16n8k16.row.col.f32.bf16.bf16.f32 "
        "{%0,%1,%2,%3}, {%4,%5,%6,%7}, {%8,%9}, {%0,%1,%2,%3};"
        : "+f"(c[0]), "+f"(c[1]), "+f"(c[2]), "+f"(c[3])
        : "r"(a[0]), "r"(a[1]), "r"(a[2]), "r"(a[3]), "r"(b0), "r"(b1));
}

__device__ __forceinline__ void cp16(uint32_t smem, const void* g) {
    asm volatile("cp.async.cg.shared.global [%0], [%1], 16;"
        :: "r"(smem), "l"(g));
}
#define CP_COMMIT() asm volatile("cp.async.commit_group;" ::: "memory")
#define CP_WAIT(n)  asm volatile("cp.async.wait_group %0;" :: "n"(n) : "memory")

__device__ __forceinline__ uint32_t pack_bf2(float a, float b) {
    __nv_bfloat162 t = __floats2bfloat162_rn(a, b);
    return *reinterpret_cast<uint32_t*>(&t);
}

__device__ __forceinline__ void split_f4(float4 v, uint2* hi, uint2* lo) {
    __nv_bfloat16 hx = __float2bfloat16(v.x), hy = __float2bfloat16(v.y);
    __nv_bfloat16 hz = __float2bfloat16(v.z), hw = __float2bfloat16(v.w);
    float lx = v.x - __bfloat162float(hx), ly = v.y - __bfloat162float(hy);
    float lz = v.z - __bfloat162float(hz), lw = v.w - __bfloat162float(hw);
    *hi = make_uint2(pack_bf2(__bfloat162float(hx), __bfloat162float(hy)),
                     pack_bf2(__bfloat162float(hz), __bfloat162float(hw)));
    *lo = make_uint2(pack_bf2(lx, ly), pack_bf2(lz, lw));
}

// ---------------------------------------------------------------------------
// converters
// ---------------------------------------------------------------------------
__global__ void conv_w_kernel(const float* __restrict__ w0, const float* __restrict__ w1)
{
    int which = blockIdx.y;
    const float* src = which ? w1 : w0;
    int i = blockIdx.x * 256 + threadIdx.x;
    float4 v = ((const float4*)src)[i];
    uint2 h, l;
    split_f4(v, &h, &l);
    ((uint2*)g_wh[which])[i] = h;
    ((uint2*)g_wl[which])[i] = l;
}

__global__ void conv_x_kernel(const float* __restrict__ x)
{
    int i = blockIdx.x * 256 + threadIdx.x;
    float4 v = __ldcs(((const float4*)x) + i);
    uint2 h, l;
    split_f4(v, &h, &l);
    __stcs(((uint2*)g_xh) + i, h);
    __stcs(((uint2*)g_xl) + i, l);
}

__global__ void bias_kernel(const float* __restrict__ table, const int* __restrict__ rpi)
{
    int idx = blockIdx.x * 256 + threadIdx.x;
    int h = idx >> 12, ij = idx & 4095;
    g_bias[idx] = table[rpi[ij] * 8 + h];
}

// ---------------------------------------------------------------------------
// cp.async 3-stage split-bf16 GEMM, 64B-pitch XOR-swizzled smem, 2 CTAs/SM.
// Software-pipelined inner loop (bh double-buffered across n-groups).
// MODE 0: write q split (Ch/Cl) at [B,H,N,64] with *0.125
// MODE 1: write fp32 row-major [M,512] to C
// ---------------------------------------------------------------------------
#define AH_OFF 0
#define AL_OFF 8192
#define WH_OFF 16384
#define WL_OFF 24576
#define G_STAGE 32768
#define G_SMEM  (3 * G_STAGE)          // 98304

template <int MODE>
__global__ void __launch_bounds__(256, 2) gemm_cp(
    const __nv_bfloat16* __restrict__ Ah, const __nv_bfloat16* __restrict__ Al,
    const __nv_bfloat16* __restrict__ Wh, const __nv_bfloat16* __restrict__ Wl,
    const float* __restrict__ bias, float* __restrict__ C,
    __nv_bfloat16* __restrict__ Ch, __nv_bfloat16* __restrict__ Cl)
{
    extern __shared__ char smem[];
    const uint32_t sbase = smem_u32(smem);
    const int tid  = threadIdx.x;
    const int wid  = tid >> 5;
    const int lane = tid & 31;
    const int wr   = wid & 3;
    const int wn   = wid >> 2;
    const int n0   = blockIdx.x;
    const int m0   = blockIdx.y;

    const int r_  = tid >> 2;
    const int c_  = tid & 3;
    const uint32_t st_off0 = r_ * 64 + ((c_ ^ ((r_ >> 1) & 3)) << 4);
    const int r2_ = r_ + 64;
    const uint32_t st_off1 = r2_ * 64 + ((c_ ^ ((r2_ >> 1) & 3)) << 4);

    const int L = lane;
    const uint32_t a_lrow = (L & 7) + ((L >> 3) & 1) * 8;
    const uint32_t b_lrow = (L & 7) + ((L >> 4) & 1) * 8;
    const uint32_t a_swz  = (a_lrow >> 1) & 3;
    const uint32_t b_swz  = (b_lrow >> 1) & 3;
    uint32_t a_col[2], b_col[2];
#pragma unroll
    for (int s = 0; s < 2; s++) {
        a_col[s] = (((uint32_t)(2 * s + (L >> 4)) ^ a_swz) << 4);
        b_col[s] = (((uint32_t)(2 * s + ((L >> 3) & 1)) ^ b_swz) << 4);
    }
    uint32_t a_row[2], b_row[4];
#pragma unroll
    for (int mt = 0; mt < 2; mt++) a_row[mt] = (wr * 32 + mt * 16 + a_lrow) * 64;
#pragma unroll
    for (int g = 0; g < 4; g++)    b_row[g]  = (wn * 64 + g * 16 + b_lrow) * 64;

    float acc[2][8][4];
#pragma unroll
    for (int mt = 0; mt < 2; mt++)
#pragma unroll
        for (int nt = 0; nt < 8; nt++)
#pragma unroll
            for (int q = 0; q < 4; q++) acc[mt][nt][q] = 0.f;

#define ISSUE(kt, buf)                                                         \
    {                                                                          \
        const uint32_t sg = sbase + (buf) * G_STAGE;                           \
        size_t ga0 = (size_t)(m0 * 128 + r_) * 512 + (kt) * 32 + c_ * 8;       \
        size_t gb0 = (size_t)(n0 * 128 + r_) * 512 + (kt) * 32 + c_ * 8;       \
        cp16(sg + AH_OFF + st_off0, Ah + ga0);                                 \
        cp16(sg + AL_OFF + st_off0, Al + ga0);                                 \
        cp16(sg + WH_OFF + st_off0, Wh + gb0);                                 \
        cp16(sg + WL_OFF + st_off0, Wl + gb0);                                 \
        size_t ga1 = ga0 + (size_t)64 * 512;                                   \
        size_t gb1 = gb0 + (size_t)64 * 512;                                   \
        cp16(sg + AH_OFF + st_off1, Ah + ga1);                                 \
        cp16(sg + AL_OFF + st_off1, Al + ga1);                                 \
        cp16(sg + WH_OFF + st_off1, Wh + gb1);                                 \
        cp16(sg + WL_OFF + st_off1, Wl + gb1);                                 \
        CP_COMMIT();                                                           \
    }

    ISSUE(0, 0);
    ISSUE(1, 1);

    for (int kt = 0; kt < 16; kt++) {
        if (kt < 15) { CP_WAIT(1); } else { CP_WAIT(0); }
        __syncthreads();
        if (kt + 2 < 16) ISSUE(kt + 2, (kt + 2) % 3);

        const uint32_t stg = sbase + (kt % 3) * G_STAGE;
#pragma unroll
        for (int s = 0; s < 2; s++) {
            uint32_t ah[2][4], al[2][4];
#pragma unroll
            for (int mt = 0; mt < 2; mt++) {
                ldsm_x4(ah[mt], stg + AH_OFF + a_row[mt] + a_col[s]);
                ldsm_x4(al[mt], stg + AL_OFF + a_row[mt] + a_col[s]);
            }
            uint32_t bh[2][4], bl[4];
            ldsm_x4(bh[0], stg + WH_OFF + b_row[0] + b_col[s]);
#pragma unroll
            for (int g = 0; g < 4; g++) {
                const int cur = g & 1, nxt = cur ^ 1;
                ldsm_x4(bl, stg + WL_OFF + b_row[g] + b_col[s]);
                // 8 MMAs on bh[cur] — also cover bl's LDSM latency
                mma16816(acc[0][2 * g],     ah[0], bh[cur][0], bh[cur][1]);
                mma16816(acc[0][2 * g + 1], ah[0], bh[cur][2], bh[cur][3]);
                mma16816(acc[1][2 * g],     ah[1], bh[cur][0], bh[cur][1]);
                mma16816(acc[1][2 * g + 1], ah[1], bh[cur][2], bh[cur][3]);
                mma16816(acc[0][2 * g],     al[0], bh[cur][0], bh[cur][1]);
                mma16816(acc[0][2 * g + 1], al[0], bh[cur][2], bh[cur][3]);
                mma16816(acc[1][2 * g],     al[1], bh[cur][0], bh[cur][1]);
                mma16816(acc[1][2 * g + 1], al[1], bh[cur][2], bh[cur][3]);
                if (g < 3) ldsm_x4(bh[nxt], stg + WH_OFF + b_row[g + 1] + b_col[s]);
                // 4 MMAs on bl while bh[nxt] is in flight
                mma16816(acc[0][2 * g],     ah[0], bl[0], bl[1]);
                mma16816(acc[0][2 * g + 1], ah[0], bl[2], bl[3]);
                mma16816(acc[1][2 * g],     ah[1], bl[0], bl[1]);
                mma16816(acc[1][2 * g + 1], ah[1], bl[2], bl[3]);
            }
        }
    }
#undef ISSUE

    const int g_  = lane >> 2;
    const int tig = lane & 3;
#pragma unroll
    for (int mt = 0; mt < 2; mt++) {
        const int mbase = m0 * 128 + wr * 32 + mt * 16 + g_;
#pragma unroll
        for (int nt = 0; nt < 8; nt++) {
            const int j = n0 * 128 + wn * 64 + nt * 8 + tig * 2;
            const float bx = __ldg(bias + j), by = __ldg(bias + j + 1);
#pragma unroll
            for (int half = 0; half < 2; half++) {
                const int m = mbase + half * 8;
                float ox = acc[mt][nt][2 * half]     + bx;
                float oy = acc[mt][nt][2 * half + 1] + by;
                if (MODE == 0) {
                    ox *= 0.125f; oy *= 0.125f;
                    int b_i = m >> 6, n_i = m & 63;
                    int h_i = j >> 6, d_i = j & 63;
                    size_t o = (((size_t)(b_i * 8 + h_i)) << 12) + (n_i << 6) + d_i;
                    __nv_bfloat16 hx = __float2bfloat16(ox);
                    __nv_bfloat16 hy = __float2bfloat16(oy);
                    *(uint32_t*)(Ch + o) =
                        pack_bf2(__bfloat162float(hx), __bfloat162float(hy));
                    *(uint32_t*)(Cl + o) =
                        pack_bf2(ox - __bfloat162float(hx), oy - __bfloat162float(hy));
                } else {
                    *(float2*)(C + (size_t)m * 512 + j) = make_float2(ox, oy);
                }
            }
        }
    }
}

// ---------------------------------------------------------------------------
// Attention via mma.sync split-bf16. One block per (b, h), 128 threads.
// Q fragments loaded directly global->registers (no smem, no ldmatrix).
// smem: Kh Kl Vh Vl only = 36864 B -> higher occupancy.
// ---------------------------------------------------------------------------
#define AP 144
#define KH_O 0
#define KL_O 9216
#define VH_O 18432
#define VL_O 27648
#define A_SMEM 36864

__global__ void __launch_bounds__(128) attn_mma(
    const float* __restrict__ pk, const float* __restrict__ pv,
    const float* __restrict__ mask,
    float* __restrict__ out_k, float* __restrict__ out_v)
{
    extern __shared__ char smem[];
    const uint32_t sb = smem_u32(smem);
    const int tid = threadIdx.x;
    const int wid = tid >> 5;
    const int lane = tid & 31;
    const int bh = blockIdx.x;
    const int b = bh >> 3, h = bh & 7;
    const int w = b & 255;

    const int g_ = lane >> 2, t4 = lane & 3;
    const int i0 = wid * 16 + g_;
    const int i1 = i0 + 8;

    // ---- Q fragments straight from global (row-major [64 rows][32 u32]) ----
    const uint32_t* qh32 = (const uint32_t*)g_qh + (size_t)bh * 2048;
    const uint32_t* ql32 = (const uint32_t*)g_ql + (size_t)bh * 2048;
    const int rA = i0 * 32, rB = i1 * 32;
    uint32_t qhf[4][4], qlf[4][4];
#pragma unroll
    for (int ks = 0; ks < 4; ks++) {
        const int o0 = ks * 8 + t4;
        qhf[ks][0] = __ldcs(qh32 + rA + o0);
        qhf[ks][1] = __ldcs(qh32 + rB + o0);
        qhf[ks][2] = __ldcs(qh32 + rA + o0 + 4);
        qhf[ks][3] = __ldcs(qh32 + rB + o0 + 4);
        qlf[ks][0] = __ldcs(ql32 + rA + o0);
        qlf[ks][1] = __ldcs(ql32 + rB + o0);
        qlf[ks][2] = __ldcs(ql32 + rA + o0 + 4);
        qlf[ks][3] = __ldcs(ql32 + rB + o0 + 4);
    }

    // ---- K/V: load + split + pass-through ----
    const float4* kg = (const float4*)(pk + (size_t)bh * 4096);
    const float4* vg = (const float4*)(pv + (size_t)bh * 4096);
    float4* ok = (float4*)(out_k + (size_t)bh * 4096);
    float4* ov = (float4*)(out_v + (size_t)bh * 4096);

#pragma unroll
    for (int i = 0; i < 8; i++) {
        int idx = tid + i * 128;
        int r = idx >> 4, c = idx & 15;
        uint32_t off = r * AP + c * 8;
        uint2 hi, lo;
        float4 k4 = __ldcs(kg + idx);
        __stcs(ok + idx, k4);
        split_f4(k4, &hi, &lo);
        *(uint2*)(smem + KH_O + off) = hi;
        *(uint2*)(smem + KL_O + off) = lo;
        float4 v4 = __ldcs(vg + idx);
        __stcs(ov + idx, v4);
        split_f4(v4, &hi, &lo);
        *(uint2*)(smem + VH_O + off) = hi;
        *(uint2*)(smem + VL_O + off) = lo;
    }
    __syncthreads();

    const uint32_t aK = sb + KH_O + ((lane & 7) + ((lane >> 4) << 3)) * AP
                                  + (((lane >> 3) & 1) << 4);
    const uint32_t aV = sb + VH_O + ((lane & 7) + (((lane >> 3) & 1) << 3)) * AP
                                  + ((lane >> 4) << 4);

    // ---- S = Q K^T (3-product split) ----
    float sacc[8][4];
#pragma unroll
    for (int nt = 0; nt < 8; nt++)
#pragma unroll
        for (int q = 0; q < 4; q++) sacc[nt][q] = 0.f;

#pragma unroll
    for (int ks = 0; ks < 4; ks++) {
#pragma unroll
        for (int jb = 0; jb < 4; jb++) {
            uint32_t kh[4], kl[4];
            uint32_t ro = jb * 16 * AP + ks * 32;
            ldsm_x4(kh, aK + ro);
            ldsm_x4(kl, aK + (KL_O - KH_O) + ro);
            mma16816(sacc[2 * jb],     qhf[ks], kh[0], kh[1]);
            mma16816(sacc[2 * jb + 1], qhf[ks], kh[2], kh[3]);
            mma16816(sacc[2 * jb],     qlf[ks], kh[0], kh[1]);
            mma16816(sacc[2 * jb + 1], qlf[ks], kh[2], kh[3]);
            mma16816(sacc[2 * jb],     qhf[ks], kl[0], kl[1]);
            mma16816(sacc[2 * jb + 1], qhf[ks], kl[2], kl[3]);
        }
    }

    // ---- bias + mask + softmax (warp-local rows) ----
    const float* mrow0 = mask + (size_t)w * 4096 + i0 * 64;
    const float* mrow1 = mask + (size_t)w * 4096 + i1 * 64;
    const float* brow0 = g_bias + h * 4096 + i0 * 64;
    const float* brow1 = g_bias + h * 4096 + i1 * 64;

#pragma unroll
    for (int nt = 0; nt < 8; nt++) {
        int j = nt * 8 + t4 * 2;
        float2 m0 = *(const float2*)(mrow0 + j);
        float2 b0 = *(const float2*)(brow0 + j);
        float2 m1 = *(const float2*)(mrow1 + j);
        float2 b1 = *(const float2*)(brow1 + j);
        sacc[nt][0] += m0.x + b0.x;
        sacc[nt][1] += m0.y + b0.y;
        sacc[nt][2] += m1.x + b1.x;
        sacc[nt][3] += m1.y + b1.y;
    }

    float mx0 = -1e30f, mx1 = -1e30f;
#pragma unroll
    for (int nt = 0; nt < 8; nt++) {
        mx0 = fmaxf(mx0, fmaxf(sacc[nt][0], sacc[nt][1]));
        mx1 = fmaxf(mx1, fmaxf(sacc[nt][2], sacc[nt][3]));
    }
    mx0 = fmaxf(mx0, __shfl_xor_sync(0xffffffffu, mx0, 1));
    mx0 = fmaxf(mx0, __shfl_xor_sync(0xffffffffu, mx0, 2));
    mx1 = fmaxf(mx1, __shfl_xor_sync(0xffffffffu, mx1, 1));
    mx1 = fmaxf(mx1, __shfl_xor_sync(0xffffffffu, mx1, 2));

    float s0 = 0.f, s1 = 0.f;
#pragma unroll
    for (int nt = 0; nt < 8; nt++) {
        sacc[nt][0] = __expf(sacc[nt][0] - mx0);
        sacc[nt][1] = __expf(sacc[nt][1] - mx0);
        sacc[nt][2] = __expf(sacc[nt][2] - mx1);
        sacc[nt][3] = __expf(sacc[nt][3] - mx1);
        s0 += sacc[nt][0] + sacc[nt][1];
        s1 += sacc[nt][2] + sacc[nt][3];
    }
    s0 += __shfl_xor_sync(0xffffffffu, s0, 1);
    s0 += __shfl_xor_sync(0xffffffffu, s0, 2);
    s1 += __shfl_xor_sync(0xffffffffu, s1, 1);
    s1 += __shfl_xor_sync(0xffffffffu, s1, 2);
    const float inv0 = 1.0f / s0, inv1 = 1.0f / s1;

    uint32_t phi0[8], plo0[8], phi1[8], plo1[8];
#pragma unroll
    for (int nt = 0; nt < 8; nt++) {
        float p0 = sacc[nt][0] * inv0, p1 = sacc[nt][1] * inv0;
        float p2 = sacc[nt][2] * inv1, p3 = sacc[nt][3] * inv1;
        __nv_bfloat16 h0 = __float2bfloat16(p0), h1 = __float2bfloat16(p1);
        __nv_bfloat16 h2 = __float2bfloat16(p2), h3 = __float2bfloat16(p3);
        phi0[nt] = pack_bf2(__bfloat162float(h0), __bfloat162float(h1));
        phi1[nt] = pack_bf2(__bfloat162float(h2), __bfloat162float(h3));
        plo0[nt] = pack_bf2(p0 - __bfloat162float(h0), p1 - __bfloat162float(h1));
        plo1[nt] = pack_bf2(p2 - __bfloat162float(h2), p3 - __bfloat162float(h3));
    }

    float oacc[8][4];
#pragma unroll
    for (int nt = 0; nt < 8; nt++)
#pragma unroll
        for (int q = 0; q < 4; q++) oacc[nt][q] = 0.f;

#pragma unroll
    for (int ks = 0; ks < 4; ks++) {
        uint32_t pa[4] = {phi0[2 * ks], phi1[2 * ks], phi0[2 * ks + 1], phi1[2 * ks + 1]};
        uint32_t pb[4] = {plo0[2 * ks], plo1[2 * ks], plo0[2 * ks + 1], plo1[2 * ks + 1]};
#pragma unroll
        for (int db = 0; db < 4; db++) {
            uint32_t vh[4], vl[4];
            uint32_t ro = ks * 16 * AP + db * 32;
            ldsm_x4_t(vh, aV + ro);
            ldsm_x4_t(vl, aV + (VL_O - VH_O) + ro);
            mma16816(oacc[2 * db],     pa, vh[0], vh[1]);
            mma16816(oacc[2 * db + 1], pa, vh[2], vh[3]);
            mma16816(oacc[2 * db],     pb, vh[0], vh[1]);
            mma16816(oacc[2 * db + 1], pb, vh[2], vh[3]);
            mma16816(oacc[2 * db],     pa, vl[0], vl[1]);
            mma16816(oacc[2 * db + 1], pa, vl[2], vl[3]);
        }
    }

    const size_t o0 = ((size_t)(b * 64 + i0)) * 512 + h * 64;
    const size_t o1 = ((size_t)(b * 64 + i1)) * 512 + h * 64;
#pragma unroll
    for (int nt = 0; nt < 8; nt++) {
        int d = nt * 8 + t4 * 2;
        float a0 = oacc[nt][0], a1 = oacc[nt][1];
        float a2 = oacc[nt][2], a3 = oacc[nt][3];
        __nv_bfloat16 h0 = __float2bfloat16(a0), h1 = __float2bfloat16(a1);
        __nv_bfloat16 h2 = __float2bfloat16(a2), h3 = __float2bfloat16(a3);
        *(uint32_t*)(g_aoh + o0 + d) = pack_bf2(__bfloat162float(h0), __bfloat162float(h1));
        *(uint32_t*)(g_aol + o0 + d) = pack_bf2(a0 - __bfloat162float(h0), a1 - __bfloat162float(h1));
        *(uint32_t*)(g_aoh + o1 + d) = pack_bf2(__bfloat162float(h2), __bfloat162float(h3));
        *(uint32_t*)(g_aol + o1 + d) = pack_bf2(a2 - __bfloat162float(h2), a3 - __bfloat162float(h3));
    }
}

// ---------------------------------------------------------------------------
extern "C" void kernel_launch(void* const* d_in, const int* in_sizes, int n_in,
                              void* d_out, int out_size)
{
    const float* x      = (const float*)d_in[0];
    const float* pk     = (const float*)d_in[1];
    const float* pv     = (const float*)d_in[2];
    const float* mask   = (const float*)d_in[3];
    const float* table  = (const float*)d_in[4];
    const int*   rpi    = (const int*)d_in[5];
    const float* qkv_w  = (const float*)d_in[6];
    const float* qkv_b  = (const float*)d_in[7];
    const float* proj_w = (const float*)d_in[8];
    const float* proj_b = (const float*)d_in[9];
    float* out = (float*)d_out;

    __nv_bfloat16 *xh, *xl, *qh, *ql, *aoh, *aol, *whp, *wlp;
    cudaGetSymbolAddress((void**)&xh,  g_xh);
    cudaGetSymbolAddress((void**)&xl,  g_xl);
    cudaGetSymbolAddress((void**)&qh,  g_qh);
    cudaGetSymbolAddress((void**)&ql,  g_ql);
    cudaGetSymbolAddress((void**)&aoh, g_aoh);
    cudaGetSymbolAddress((void**)&aol, g_aol);
    cudaGetSymbolAddress((void**)&whp, g_wh);
    cudaGetSymbolAddress((void**)&wlp, g_wl);

    static bool attr_set = false;
    if (!attr_set) {
        cudaFuncSetAttribute(gemm_cp<0>, cudaFuncAttributeMaxDynamicSharedMemorySize, G_SMEM);
        cudaFuncSetAttribute(gemm_cp<1>, cudaFuncAttributeMaxDynamicSharedMemorySize, G_SMEM);
        cudaFuncSetAttribute(attn_mma,   cudaFuncAttributeMaxDynamicSharedMemorySize, A_SMEM);
        attr_set = true;
    }

    conv_w_kernel<<<dim3(256, 2), 256>>>(qkv_w, proj_w);
    bias_kernel<<<128, 256>>>(table, rpi);
    conv_x_kernel<<<131072, 256>>>(x);

    dim3 ggrid(4, 2048);   // N/128 x M/128
    gemm_cp<0><<<ggrid, 256, G_SMEM>>>(xh, xl, whp, wlp, qkv_b,
                                       nullptr, qh, ql);

    attn_mma<<<32768, 128, A_SMEM>>>(pk, pv, mask, out + (size_t)PKE,
                                     out + (size_t)2 * PKE);

    gemm_cp<1><<<ggrid, 256, G_SMEM>>>(aoh, aol, whp + 262144, wlp + 262144, proj_b,
                                       out, nullptr, nullptr);
}

// round 11
// speedup vs baseline: 1.6852x; 1.2960x over previous
#include <cuda_runtime.h>
#include <cuda_fp16.h>
#include <cstdint>

#define PKE 134217728   // 4096*8*64*64

// Scratch (__device__ globals; allocation-free rule)
__device__ __half g_xh[PKE], g_xl[PKE];     // x split (hi/lo fp16)
__device__ __half g_qh[PKE], g_ql[PKE];     // q split, [B,H,N,64], pre-scaled
__device__ __half g_aoh[PKE], g_aol[PKE];   // attn out split, [B*N,512]
__device__ __half g_wh[2][262144];          // weight hi only: [0]=qkv_w, [1]=proj_w
__device__ float g_bias[32768];             // bias_full[h][i][j]

// ---------------------------------------------------------------------------
// helpers
// ---------------------------------------------------------------------------
__device__ __forceinline__ uint32_t smem_u32(const void* p) {
    uint32_t a;
    asm("{ .reg .u64 t; cvta.to.shared.u64 t, %1; cvt.u32.u64 %0, t; }"
        : "=r"(a) : "l"(p));
    return a;
}

__device__ __forceinline__ void ldsm_x4(uint32_t* d, uint32_t addr) {
    asm volatile("ldmatrix.sync.aligned.m8n8.x4.shared.b16 {%0,%1,%2,%3}, [%4];"
        : "=r"(d[0]), "=r"(d[1]), "=r"(d[2]), "=r"(d[3]) : "r"(addr));
}

__device__ __forceinline__ void ldsm_x4_t(uint32_t* d, uint32_t addr) {
    asm volatile("ldmatrix.sync.aligned.m8n8.x4.trans.shared.b16 {%0,%1,%2,%3}, [%4];"
        : "=r"(d[0]), "=r"(d[1]), "=r"(d[2]), "=r"(d[3]) : "r"(addr));
}

__device__ __forceinline__ void mma16816(float* c, const uint32_t* a,
                                         uint32_t b0, uint32_t b1) {
    asm volatile("mma.sync.aligned.m16n8k16.row.col.f32.f16.f16.f32 "
        "{%0,%1,%2,%3}, {%4,%5,%6,%7}, {%8,%9}, {%0,%1,%2,%3};"
        : "+f"(c[0]), "+f"(c[1]), "+f"(c[2]), "+f"(c[3])
        : "r"(a[0]), "r"(a[1]), "r"(a[2]), "r"(a[3]), "r"(b0), "r"(b1));
}

__device__ __forceinline__ void cp16(uint32_t smem, const void* g) {
    asm volatile("cp.async.cg.shared.global [%0], [%1], 16;"
        :: "r"(smem), "l"(g));
}
#define CP_COMMIT() asm volatile("cp.async.commit_group;" ::: "memory")
#define CP_WAIT(n)  asm volatile("cp.async.wait_group %0;" :: "n"(n) : "memory")

__device__ __forceinline__ uint32_t pack_h2(float a, float b) {
    __half2 t = __floats2half2_rn(a, b);
    return *reinterpret_cast<uint32_t*>(&t);
}

// split a float4 into fp16 hi (uint2) and lo (uint2)
__device__ __forceinline__ void split_f4(float4 v, uint2* hi, uint2* lo) {
    __half hx = __float2half(v.x), hy = __float2half(v.y);
    __half hz = __float2half(v.z), hw = __float2half(v.w);
    float lx = v.x - __half2float(hx), ly = v.y - __half2float(hy);
    float lz = v.z - __half2float(hz), lw = v.w - __half2float(hw);
    *hi = make_uint2(pack_h2(__half2float(hx), __half2float(hy)),
                     pack_h2(__half2float(hz), __half2float(hw)));
    *lo = make_uint2(pack_h2(lx, ly), pack_h2(lz, lw));
}

// float4 -> fp16 hi only
__device__ __forceinline__ uint2 cvt_f4(float4 v) {
    return make_uint2(pack_h2(v.x, v.y), pack_h2(v.z, v.w));
}

// ---------------------------------------------------------------------------
// converters
// ---------------------------------------------------------------------------
__global__ void conv_w_kernel(const float* __restrict__ w0, const float* __restrict__ w1)
{
    int which = blockIdx.y;
    const float* src = which ? w1 : w0;
    int i = blockIdx.x * 256 + threadIdx.x;
    float4 v = ((const float4*)src)[i];
    ((uint2*)g_wh[which])[i] = cvt_f4(v);
}

__global__ void conv_x_kernel(const float* __restrict__ x)
{
    int i = blockIdx.x * 256 + threadIdx.x;
    float4 v = __ldcs(((const float4*)x) + i);
    uint2 h, l;
    split_f4(v, &h, &l);
    __stcs(((uint2*)g_xh) + i, h);
    __stcs(((uint2*)g_xl) + i, l);
}

__global__ void bias_kernel(const float* __restrict__ table, const int* __restrict__ rpi)
{
    int idx = blockIdx.x * 256 + threadIdx.x;
    int h = idx >> 12, ij = idx & 4095;
    g_bias[idx] = table[rpi[ij] * 8 + h];
}

// ---------------------------------------------------------------------------
// cp.async 3-stage fp16 2-product GEMM:  C = (Ah+Al) * Wh^T + bias
// 64B-pitch XOR-swizzled smem, 2 CTAs/SM. CTA tile 128x128, K-chunk 32.
// smem per stage: Ah | Al | Wh, each 128 rows x 64 B = 24576 B.
// MODE 0: write q split (Ch/Cl fp16) at [B,H,N,64] with *0.125
// MODE 1: write fp32 row-major [M,512] to C
// ---------------------------------------------------------------------------
#define AH_OFF 0
#define AL_OFF 8192
#define WH_OFF 16384
#define G_STAGE 24576
#define G_SMEM  (3 * G_STAGE)          // 73728

template <int MODE>
__global__ void __launch_bounds__(256, 2) gemm_cp(
    const __half* __restrict__ Ah, const __half* __restrict__ Al,
    const __half* __restrict__ Wh,
    const float* __restrict__ bias, float* __restrict__ C,
    __half* __restrict__ Ch, __half* __restrict__ Cl)
{
    extern __shared__ char smem[];
    const uint32_t sbase = smem_u32(smem);
    const int tid  = threadIdx.x;
    const int wid  = tid >> 5;
    const int lane = tid & 31;
    const int wr   = wid & 3;
    const int wn   = wid >> 2;
    const int n0   = blockIdx.x;
    const int m0   = blockIdx.y;

    const int r_  = tid >> 2;
    const int c_  = tid & 3;
    const uint32_t st_off0 = r_ * 64 + ((c_ ^ ((r_ >> 1) & 3)) << 4);
    const int r2_ = r_ + 64;
    const uint32_t st_off1 = r2_ * 64 + ((c_ ^ ((r2_ >> 1) & 3)) << 4);

    const int L = lane;
    const uint32_t a_lrow = (L & 7) + ((L >> 3) & 1) * 8;
    const uint32_t b_lrow = (L & 7) + ((L >> 4) & 1) * 8;
    const uint32_t a_swz  = (a_lrow >> 1) & 3;
    const uint32_t b_swz  = (b_lrow >> 1) & 3;
    uint32_t a_col[2], b_col[2];
#pragma unroll
    for (int s = 0; s < 2; s++) {
        a_col[s] = (((uint32_t)(2 * s + (L >> 4)) ^ a_swz) << 4);
        b_col[s] = (((uint32_t)(2 * s + ((L >> 3) & 1)) ^ b_swz) << 4);
    }
    uint32_t a_row[2], b_row[4];
#pragma unroll
    for (int mt = 0; mt < 2; mt++) a_row[mt] = (wr * 32 + mt * 16 + a_lrow) * 64;
#pragma unroll
    for (int g = 0; g < 4; g++)    b_row[g]  = (wn * 64 + g * 16 + b_lrow) * 64;

    float acc[2][8][4];
#pragma unroll
    for (int mt = 0; mt < 2; mt++)
#pragma unroll
        for (int nt = 0; nt < 8; nt++)
#pragma unroll
            for (int q = 0; q < 4; q++) acc[mt][nt][q] = 0.f;

#define ISSUE(kt, buf)                                                         \
    {                                                                          \
        const uint32_t sg = sbase + (buf) * G_STAGE;                           \
        size_t ga0 = (size_t)(m0 * 128 + r_) * 512 + (kt) * 32 + c_ * 8;       \
        size_t gb0 = (size_t)(n0 * 128 + r_) * 512 + (kt) * 32 + c_ * 8;       \
        cp16(sg + AH_OFF + st_off0, Ah + ga0);                                 \
        cp16(sg + AL_OFF + st_off0, Al + ga0);                                 \
        cp16(sg + WH_OFF + st_off0, Wh + gb0);                                 \
        size_t ga1 = ga0 + (size_t)64 * 512;                                   \
        size_t gb1 = gb0 + (size_t)64 * 512;                                   \
        cp16(sg + AH_OFF + st_off1, Ah + ga1);                                 \
        cp16(sg + AL_OFF + st_off1, Al + ga1);                                 \
        cp16(sg + WH_OFF + st_off1, Wh + gb1);                                 \
        CP_COMMIT();                                                           \
    }

    ISSUE(0, 0);
    ISSUE(1, 1);

    for (int kt = 0; kt < 16; kt++) {
        if (kt < 15) { CP_WAIT(1); } else { CP_WAIT(0); }
        __syncthreads();
        if (kt + 2 < 16) ISSUE(kt + 2, (kt + 2) % 3);

        const uint32_t stg = sbase + (kt % 3) * G_STAGE;
#pragma unroll
        for (int s = 0; s < 2; s++) {
            uint32_t ah[2][4], al[2][4];
#pragma unroll
            for (int mt = 0; mt < 2; mt++) {
                ldsm_x4(ah[mt], stg + AH_OFF + a_row[mt] + a_col[s]);
                ldsm_x4(al[mt], stg + AL_OFF + a_row[mt] + a_col[s]);
            }
            uint32_t bh[2][4];
            ldsm_x4(bh[0], stg + WH_OFF + b_row[0] + b_col[s]);
#pragma unroll
            for (int g = 0; g < 4; g++) {
                const int cur = g & 1, nxt = cur ^ 1;
                if (g < 3) ldsm_x4(bh[nxt], stg + WH_OFF + b_row[g + 1] + b_col[s]);
                mma16816(acc[0][2 * g],     ah[0], bh[cur][0], bh[cur][1]);
                mma16816(acc[0][2 * g + 1], ah[0], bh[cur][2], bh[cur][3]);
                mma16816(acc[1][2 * g],     ah[1], bh[cur][0], bh[cur][1]);
                mma16816(acc[1][2 * g + 1], ah[1], bh[cur][2], bh[cur][3]);
                mma16816(acc[0][2 * g],     al[0], bh[cur][0], bh[cur][1]);
                mma16816(acc[0][2 * g + 1], al[0], bh[cur][2], bh[cur][3]);
                mma16816(acc[1][2 * g],     al[1], bh[cur][0], bh[cur][1]);
                mma16816(acc[1][2 * g + 1], al[1], bh[cur][2], bh[cur][3]);
            }
        }
    }
#undef ISSUE

    const int g_  = lane >> 2;
    const int tig = lane & 3;
#pragma unroll
    for (int mt = 0; mt < 2; mt++) {
        const int mbase = m0 * 128 + wr * 32 + mt * 16 + g_;
#pragma unroll
        for (int nt = 0; nt < 8; nt++) {
            const int j = n0 * 128 + wn * 64 + nt * 8 + tig * 2;
            const float bx = __ldg(bias + j), by = __ldg(bias + j + 1);
#pragma unroll
            for (int half = 0; half < 2; half++) {
                const int m = mbase + half * 8;
                float ox = acc[mt][nt][2 * half]     + bx;
                float oy = acc[mt][nt][2 * half + 1] + by;
                if (MODE == 0) {
                    ox *= 0.125f; oy *= 0.125f;
                    int b_i = m >> 6, n_i = m & 63;
                    int h_i = j >> 6, d_i = j & 63;
                    size_t o = (((size_t)(b_i * 8 + h_i)) << 12) + (n_i << 6) + d_i;
                    __half hx = __float2half(ox);
                    __half hy = __float2half(oy);
                    *(uint32_t*)(Ch + o) =
                        pack_h2(__half2float(hx), __half2float(hy));
                    *(uint32_t*)(Cl + o) =
                        pack_h2(ox - __half2float(hx), oy - __half2float(hy));
                } else {
                    *(float2*)(C + (size_t)m * 512 + j) = make_float2(ox, oy);
                }
            }
        }
    }
}

// ---------------------------------------------------------------------------
// Attention via mma.sync fp16 2-product. One block per (b, h), 128 threads.
// Q fragments loaded directly global->registers; only K_hi / V_hi in smem.
// smem = 18432 B -> high occupancy. Fuses p_k/p_v pass-through.
// ---------------------------------------------------------------------------
#define AP 144
#define KH_O 0
#define VH_O 9216
#define A_SMEM 18432

__global__ void __launch_bounds__(128) attn_mma(
    const float* __restrict__ pk, const float* __restrict__ pv,
    const float* __restrict__ mask,
    float* __restrict__ out_k, float* __restrict__ out_v)
{
    extern __shared__ char smem[];
    const uint32_t sb = smem_u32(smem);
    const int tid = threadIdx.x;
    const int wid = tid >> 5;
    const int lane = tid & 31;
    const int bh = blockIdx.x;
    const int b = bh >> 3, h = bh & 7;
    const int w = b & 255;

    const int g_ = lane >> 2, t4 = lane & 3;
    const int i0 = wid * 16 + g_;
    const int i1 = i0 + 8;

    // ---- Q fragments straight from global (row-major [64 rows][32 u32]) ----
    const uint32_t* qh32 = (const uint32_t*)g_qh + (size_t)bh * 2048;
    const uint32_t* ql32 = (const uint32_t*)g_ql + (size_t)bh * 2048;
    const int rA = i0 * 32, rB = i1 * 32;
    uint32_t qhf[4][4], qlf[4][4];
#pragma unroll
    for (int ks = 0; ks < 4; ks++) {
        const int o0 = ks * 8 + t4;
        qhf[ks][0] = __ldcs(qh32 + rA + o0);
        qhf[ks][1] = __ldcs(qh32 + rB + o0);
        qhf[ks][2] = __ldcs(qh32 + rA + o0 + 4);
        qhf[ks][3] = __ldcs(qh32 + rB + o0 + 4);
        qlf[ks][0] = __ldcs(ql32 + rA + o0);
        qlf[ks][1] = __ldcs(ql32 + rB + o0);
        qlf[ks][2] = __ldcs(ql32 + rA + o0 + 4);
        qlf[ks][3] = __ldcs(ql32 + rB + o0 + 4);
    }

    // ---- K/V: load + convert(hi) + pass-through ----
    const float4* kg = (const float4*)(pk + (size_t)bh * 4096);
    const float4* vg = (const float4*)(pv + (size_t)bh * 4096);
    float4* ok = (float4*)(out_k + (size_t)bh * 4096);
    float4* ov = (float4*)(out_v + (size_t)bh * 4096);

#pragma unroll
    for (int i = 0; i < 8; i++) {
        int idx = tid + i * 128;
        int r = idx >> 4, c = idx & 15;
        uint32_t off = r * AP + c * 8;
        float4 k4 = __ldcs(kg + idx);
        __stcs(ok + idx, k4);
        *(uint2*)(smem + KH_O + off) = cvt_f4(k4);
        float4 v4 = __ldcs(vg + idx);
        __stcs(ov + idx, v4);
        *(uint2*)(smem + VH_O + off) = cvt_f4(v4);
    }
    __syncthreads();

    const uint32_t aK = sb + KH_O + ((lane & 7) + ((lane >> 4) << 3)) * AP
                                  + (((lane >> 3) & 1) << 4);
    const uint32_t aV = sb + VH_O + ((lane & 7) + (((lane >> 3) & 1) << 3)) * AP
                                  + ((lane >> 4) << 4);

    // ---- S = Q K^T (2-product) ----
    float sacc[8][4];
#pragma unroll
    for (int nt = 0; nt < 8; nt++)
#pragma unroll
        for (int q = 0; q < 4; q++) sacc[nt][q] = 0.f;

#pragma unroll
    for (int ks = 0; ks < 4; ks++) {
#pragma unroll
        for (int jb = 0; jb < 4; jb++) {
            uint32_t kh[4];
            ldsm_x4(kh, aK + jb * 16 * AP + ks * 32);
            mma16816(sacc[2 * jb],     qhf[ks], kh[0], kh[1]);
            mma16816(sacc[2 * jb + 1], qhf[ks], kh[2], kh[3]);
            mma16816(sacc[2 * jb],     qlf[ks], kh[0], kh[1]);
            mma16816(sacc[2 * jb + 1], qlf[ks], kh[2], kh[3]);
        }
    }

    // ---- bias + mask + softmax (warp-local rows) ----
    const float* mrow0 = mask + (size_t)w * 4096 + i0 * 64;
    const float* mrow1 = mask + (size_t)w * 4096 + i1 * 64;
    const float* brow0 = g_bias + h * 4096 + i0 * 64;
    const float* brow1 = g_bias + h * 4096 + i1 * 64;

#pragma unroll
    for (int nt = 0; nt < 8; nt++) {
        int j = nt * 8 + t4 * 2;
        float2 m0 = *(const float2*)(mrow0 + j);
        float2 b0 = *(const float2*)(brow0 + j);
        float2 m1 = *(const float2*)(mrow1 + j);
        float2 b1 = *(const float2*)(brow1 + j);
        sacc[nt][0] += m0.x + b0.x;
        sacc[nt][1] += m0.y + b0.y;
        sacc[nt][2] += m1.x + b1.x;
        sacc[nt][3] += m1.y + b1.y;
    }

    float mx0 = -1e30f, mx1 = -1e30f;
#pragma unroll
    for (int nt = 0; nt < 8; nt++) {
        mx0 = fmaxf(mx0, fmaxf(sacc[nt][0], sacc[nt][1]));
        mx1 = fmaxf(mx1, fmaxf(sacc[nt][2], sacc[nt][3]));
    }
    mx0 = fmaxf(mx0, __shfl_xor_sync(0xffffffffu, mx0, 1));
    mx0 = fmaxf(mx0, __shfl_xor_sync(0xffffffffu, mx0, 2));
    mx1 = fmaxf(mx1, __shfl_xor_sync(0xffffffffu, mx1, 1));
    mx1 = fmaxf(mx1, __shfl_xor_sync(0xffffffffu, mx1, 2));

    float s0 = 0.f, s1 = 0.f;
#pragma unroll
    for (int nt = 0; nt < 8; nt++) {
        sacc[nt][0] = __expf(sacc[nt][0] - mx0);
        sacc[nt][1] = __expf(sacc[nt][1] - mx0);
        sacc[nt][2] = __expf(sacc[nt][2] - mx1);
        sacc[nt][3] = __expf(sacc[nt][3] - mx1);
        s0 += sacc[nt][0] + sacc[nt][1];
        s1 += sacc[nt][2] + sacc[nt][3];
    }
    s0 += __shfl_xor_sync(0xffffffffu, s0, 1);
    s0 += __shfl_xor_sync(0xffffffffu, s0, 2);
    s1 += __shfl_xor_sync(0xffffffffu, s1, 1);
    s1 += __shfl_xor_sync(0xffffffffu, s1, 2);
    const float inv0 = 1.0f / s0, inv1 = 1.0f / s1;

    // ---- P -> fp16 hi/lo fragments (registers only) ----
    uint32_t phi0[8], plo0[8], phi1[8], plo1[8];
#pragma unroll
    for (int nt = 0; nt < 8; nt++) {
        float p0 = sacc[nt][0] * inv0, p1 = sacc[nt][1] * inv0;
        float p2 = sacc[nt][2] * inv1, p3 = sacc[nt][3] * inv1;
        __half h0 = __float2half(p0), h1 = __float2half(p1);
        __half h2 = __float2half(p2), h3 = __float2half(p3);
        phi0[nt] = pack_h2(__half2float(h0), __half2float(h1));
        phi1[nt] = pack_h2(__half2float(h2), __half2float(h3));
        plo0[nt] = pack_h2(p0 - __half2float(h0), p1 - __half2float(h1));
        plo1[nt] = pack_h2(p2 - __half2float(h2), p3 - __half2float(h3));
    }

    // ---- O = P V (2-product), V frags via ldmatrix.trans ----
    float oacc[8][4];
#pragma unroll
    for (int nt = 0; nt < 8; nt++)
#pragma unroll
        for (int q = 0; q < 4; q++) oacc[nt][q] = 0.f;

#pragma unroll
    for (int ks = 0; ks < 4; ks++) {
        uint32_t pa[4] = {phi0[2 * ks], phi1[2 * ks], phi0[2 * ks + 1], phi1[2 * ks + 1]};
        uint32_t pb[4] = {plo0[2 * ks], plo1[2 * ks], plo0[2 * ks + 1], plo1[2 * ks + 1]};
#pragma unroll
        for (int db = 0; db < 4; db++) {
            uint32_t vh[4];
            ldsm_x4_t(vh, aV + ks * 16 * AP + db * 32);
            mma16816(oacc[2 * db],     pa, vh[0], vh[1]);
            mma16816(oacc[2 * db + 1], pa, vh[2], vh[3]);
            mma16816(oacc[2 * db],     pb, vh[0], vh[1]);
            mma16816(oacc[2 * db + 1], pb, vh[2], vh[3]);
        }
    }

    // ---- write attn out pre-split fp16 hi/lo ----
    const size_t o0 = ((size_t)(b * 64 + i0)) * 512 + h * 64;
    const size_t o1 = ((size_t)(b * 64 + i1)) * 512 + h * 64;
#pragma unroll
    for (int nt = 0; nt < 8; nt++) {
        int d = nt * 8 + t4 * 2;
        float a0 = oacc[nt][0], a1 = oacc[nt][1];
        float a2 = oacc[nt][2], a3 = oacc[nt][3];
        __half h0 = __float2half(a0), h1 = __float2half(a1);
        __half h2 = __float2half(a2), h3 = __float2half(a3);
        *(uint32_t*)(g_aoh + o0 + d) = pack_h2(__half2float(h0), __half2float(h1));
        *(uint32_t*)(g_aol + o0 + d) = pack_h2(a0 - __half2float(h0), a1 - __half2float(h1));
        *(uint32_t*)(g_aoh + o1 + d) = pack_h2(__half2float(h2), __half2float(h3));
        *(uint32_t*)(g_aol + o1 + d) = pack_h2(a2 - __half2float(h2), a3 - __half2float(h3));
    }
}

// ---------------------------------------------------------------------------
extern "C" void kernel_launch(void* const* d_in, const int* in_sizes, int n_in,
                              void* d_out, int out_size)
{
    const float* x      = (const float*)d_in[0];
    const float* pk     = (const float*)d_in[1];
    const float* pv     = (const float*)d_in[2];
    const float* mask   = (const float*)d_in[3];
    const float* table  = (const float*)d_in[4];
    const int*   rpi    = (const int*)d_in[5];
    const float* qkv_w  = (const float*)d_in[6];
    const float* qkv_b  = (const float*)d_in[7];
    const float* proj_w = (const float*)d_in[8];
    const float* proj_b = (const float*)d_in[9];
    float* out = (float*)d_out;

    __half *xh, *xl, *qh, *ql, *aoh, *aol, *whp;
    cudaGetSymbolAddress((void**)&xh,  g_xh);
    cudaGetSymbolAddress((void**)&xl,  g_xl);
    cudaGetSymbolAddress((void**)&qh,  g_qh);
    cudaGetSymbolAddress((void**)&ql,  g_ql);
    cudaGetSymbolAddress((void**)&aoh, g_aoh);
    cudaGetSymbolAddress((void**)&aol, g_aol);
    cudaGetSymbolAddress((void**)&whp, g_wh);

    static bool attr_set = false;
    if (!attr_set) {
        cudaFuncSetAttribute(gemm_cp<0>, cudaFuncAttributeMaxDynamicSharedMemorySize, G_SMEM);
        cudaFuncSetAttribute(gemm_cp<1>, cudaFuncAttributeMaxDynamicSharedMemorySize, G_SMEM);
        cudaFuncSetAttribute(attn_mma,   cudaFuncAttributeMaxDynamicSharedMemorySize, A_SMEM);
        attr_set = true;
    }

    conv_w_kernel<<<dim3(256, 2), 256>>>(qkv_w, proj_w);
    bias_kernel<<<128, 256>>>(table, rpi);
    conv_x_kernel<<<131072, 256>>>(x);

    dim3 ggrid(4, 2048);   // N/128 x M/128
    gemm_cp<0><<<ggrid, 256, G_SMEM>>>(xh, xl, whp, qkv_b,
                                       nullptr, qh, ql);

    attn_mma<<<32768, 128, A_SMEM>>>(pk, pv, mask, out + (size_t)PKE,
                                     out + (size_t)2 * PKE);

    gemm_cp<1><<<ggrid, 256, G_SMEM>>>(aoh, aol, whp + 262144, proj_b,
                                       out, nullptr, nullptr);
}